// round 3
// baseline (speedup 1.0000x reference)
#include <cuda_runtime.h>
#include <cuda_bf16.h>

typedef unsigned int uint;

// ---------------- scratch (device globals; no allocs allowed) ----------------
__device__ float g_q[2048L * 64 * 256];    // 128 MB : q projection
__device__ float g_kv[4096L * 64 * 512];   // 512 MB : kv projection
__device__ float g_att[4096L * 64 * 256];  // 256 MB : attention output (pre-proj)

#define DEV_INLINE __device__ __forceinline__

DEV_INLINE void mma16816(float* d, const uint* a, const uint* b) {
    asm volatile(
        "mma.sync.aligned.m16n8k16.row.col.f32.bf16.bf16.f32 "
        "{%0,%1,%2,%3}, {%4,%5,%6,%7}, {%8,%9}, {%0,%1,%2,%3};\n"
        : "+f"(d[0]), "+f"(d[1]), "+f"(d[2]), "+f"(d[3])
        : "r"(a[0]), "r"(a[1]), "r"(a[2]), "r"(a[3]), "r"(b[0]), "r"(b[1]));
}

DEV_INLINE void ldsm_x4(uint* r, uint addr) {
    asm volatile("ldmatrix.sync.aligned.m8n8.x4.shared.b16 {%0,%1,%2,%3}, [%4];"
                 : "=r"(r[0]), "=r"(r[1]), "=r"(r[2]), "=r"(r[3]) : "r"(addr));
}

DEV_INLINE uint sm_u32(const void* p) {
    uint a;
    asm("{ .reg .u64 t; cvta.to.shared.u64 t, %1; cvt.u32.u64 %0, t; }"
        : "=r"(a) : "l"(p));
    return a;
}

DEV_INLINE uint lds_u32(const __nv_bfloat16* p) {
    return *reinterpret_cast<const uint*>(p);
}

DEV_INLINE void split_store(float x, float y, __nv_bfloat16* hi_p, __nv_bfloat16* lo_p) {
    __nv_bfloat162 h = __floats2bfloat162_rn(x, y);
    __nv_bfloat162 l = __floats2bfloat162_rn(x - __bfloat162float(h.x),
                                             y - __bfloat162float(h.y));
    *reinterpret_cast<__nv_bfloat162*>(hi_p) = h;
    *reinterpret_cast<__nv_bfloat162*>(lo_p) = l;
}

DEV_INLINE void packsplit(float x, float y, uint& hi, uint& lo) {
    __nv_bfloat162 h = __floats2bfloat162_rn(x, y);
    __nv_bfloat162 l = __floats2bfloat162_rn(x - __bfloat162float(h.x),
                                             y - __bfloat162float(h.y));
    hi = *reinterpret_cast<uint*>(&h);
    lo = *reinterpret_cast<uint*>(&l);
}

DEV_INLINE void pack8(float4 a, float4 b, uint4& hi, uint4& lo) {
    __nv_bfloat162 h0 = __floats2bfloat162_rn(a.x, a.y);
    __nv_bfloat162 h1 = __floats2bfloat162_rn(a.z, a.w);
    __nv_bfloat162 h2 = __floats2bfloat162_rn(b.x, b.y);
    __nv_bfloat162 h3 = __floats2bfloat162_rn(b.z, b.w);
    __nv_bfloat162 l0 = __floats2bfloat162_rn(a.x - __bfloat162float(h0.x),
                                              a.y - __bfloat162float(h0.y));
    __nv_bfloat162 l1 = __floats2bfloat162_rn(a.z - __bfloat162float(h1.x),
                                              a.w - __bfloat162float(h1.y));
    __nv_bfloat162 l2 = __floats2bfloat162_rn(b.x - __bfloat162float(h2.x),
                                              b.y - __bfloat162float(h2.y));
    __nv_bfloat162 l3 = __floats2bfloat162_rn(b.z - __bfloat162float(h3.x),
                                              b.w - __bfloat162float(h3.y));
    hi.x = *reinterpret_cast<uint*>(&h0); hi.y = *reinterpret_cast<uint*>(&h1);
    hi.z = *reinterpret_cast<uint*>(&h2); hi.w = *reinterpret_cast<uint*>(&h3);
    lo.x = *reinterpret_cast<uint*>(&l0); lo.y = *reinterpret_cast<uint*>(&l1);
    lo.z = *reinterpret_cast<uint*>(&l2); lo.w = *reinterpret_cast<uint*>(&l3);
}

// =============================================================================
// GEMM: C[M,N] = A[M,256] @ W[N,256]^T + bias[N]  (bf16x3 compensated)
// CTA: 512 threads (16 warps, 4m x 4n), tile BM=128 x BN=256, BK=32, 2 stages.
// Warp tile 32x64 (acc[2][8][4]). ldmatrix.x4 fragment loads.
// smem stage: Ahi(128x40) Alo Bhi(256x40) Blo = 30720 el = 61440 B; x2 = 120 KB.
// =============================================================================
__global__ __launch_bounds__(512, 1) void gemm_kernel(
    const float* __restrict__ A, const float* __restrict__ W,
    const float* __restrict__ bias, float* __restrict__ C, int ldC)
{
    constexpr int LDT = 40;                 // smem row stride (el), 80 B
    constexpr int STG_B = 61440;            // stage bytes
    extern __shared__ char smc[];
    const uint smb = sm_u32(smc);

    const int tid = threadIdx.x;
    const int warp = tid >> 5, lane = tid & 31;
    const int wm = warp & 3, wn = warp >> 2;
    const int g = lane >> 2, tc = lane & 3;
    const int quad = lane >> 3, qr = lane & 7;
    const int m0 = blockIdx.y * 128, n0 = blockIdx.x * 256;

    auto load_stage = [&](int kt, int s) {
        char* base = smc + s * STG_B;
        const int k0 = kt * 32;
        {   // A: 128 x 32 = 512 units of 8 floats; 1 per thread
            int r = tid >> 2, cu = (tid & 3) * 8;
            const float* p = A + (size_t)(m0 + r) * 256 + k0 + cu;
            float4 f0 = *reinterpret_cast<const float4*>(p);
            float4 f1 = *reinterpret_cast<const float4*>(p + 4);
            uint4 hi, lo; pack8(f0, f1, hi, lo);
            uint off = (uint)(r * 80 + cu * 2);
            *reinterpret_cast<uint4*>(base + off) = hi;
            *reinterpret_cast<uint4*>(base + 10240 + off) = lo;
        }
        #pragma unroll
        for (int v = 0; v < 2; v++) {       // B: 256 x 32 = 1024 units; 2 per thread
            int un = tid + v * 512;
            int r = un >> 2, cu = (un & 3) * 8;
            const float* p = W + (size_t)(n0 + r) * 256 + k0 + cu;
            float4 f0 = *reinterpret_cast<const float4*>(p);
            float4 f1 = *reinterpret_cast<const float4*>(p + 4);
            uint4 hi, lo; pack8(f0, f1, hi, lo);
            uint off = (uint)(r * 80 + cu * 2);
            *reinterpret_cast<uint4*>(base + 20480 + off) = hi;
            *reinterpret_cast<uint4*>(base + 40960 + off) = lo;
        }
    };

    float acc[2][8][4];
    #pragma unroll
    for (int i = 0; i < 2; i++)
        #pragma unroll
        for (int j = 0; j < 8; j++)
            #pragma unroll
            for (int e = 0; e < 4; e++) acc[i][j][e] = 0.f;

    load_stage(0, 0);
    __syncthreads();

    #pragma unroll 2
    for (int kt = 0; kt < 8; kt++) {
        if (kt < 7) load_stage(kt + 1, (kt + 1) & 1);

        const uint sb = smb + (kt & 1) * STG_B;
        #pragma unroll
        for (int kk = 0; kk < 2; kk++) {
            const int kc = kk * 16;
            uint ah[2][4], al[2][4];
            #pragma unroll
            for (int mi = 0; mi < 2; mi++) {
                int row = wm * 32 + mi * 16 + (quad & 1) * 8 + qr;
                int col = kc + (quad >> 1) * 8;
                uint ad = sb + (uint)(row * 80 + col * 2);
                ldsm_x4(ah[mi], ad);
                ldsm_x4(al[mi], ad + 10240);
            }
            #pragma unroll
            for (int njp = 0; njp < 4; njp++) {
                int row = wn * 64 + njp * 16 + (quad >> 1) * 8 + qr;
                int col = kc + (quad & 1) * 8;
                uint bd = sb + 20480u + (uint)(row * 80 + col * 2);
                uint bh[4], bl[4];
                ldsm_x4(bh, bd);
                ldsm_x4(bl, bd + 20480);
                #pragma unroll
                for (int mi = 0; mi < 2; mi++) {
                    mma16816(acc[mi][2 * njp], ah[mi], bh);
                    mma16816(acc[mi][2 * njp], al[mi], bh);
                    mma16816(acc[mi][2 * njp], ah[mi], bl);
                    mma16816(acc[mi][2 * njp + 1], ah[mi], bh + 2);
                    mma16816(acc[mi][2 * njp + 1], al[mi], bh + 2);
                    mma16816(acc[mi][2 * njp + 1], ah[mi], bl + 2);
                }
            }
        }
        __syncthreads();
    }

    #pragma unroll
    for (int mi = 0; mi < 2; mi++) {
        #pragma unroll
        for (int nj = 0; nj < 8; nj++) {
            int row = m0 + wm * 32 + mi * 16 + g;
            int col = n0 + wn * 64 + nj * 8 + tc * 2;
            float b0 = __ldg(bias + col), b1 = __ldg(bias + col + 1);
            *reinterpret_cast<float2*>(C + (size_t)row * ldC + col) =
                make_float2(acc[mi][nj][0] + b0, acc[mi][nj][1] + b1);
            *reinterpret_cast<float2*>(C + (size_t)(row + 8) * ldC + col) =
                make_float2(acc[mi][nj][2] + b0, acc[mi][nj][3] + b1);
        }
    }
}

// =============================================================================
// Fused attention v2: one CTA per (bt, head-group of 4). 256 threads = 8 warps
// = 2 warps/head. smem ~113.7 KB -> 2 CTAs/SM. bf16x3 math unchanged.
// =============================================================================
__global__ __launch_bounds__(256, 2) void attn_kernel(const float* __restrict__ rpb)
{
    extern __shared__ __nv_bfloat16 sm[];
    // el offsets: qhi 0 | qlo 8704 | khi 17408 | klo 26112 | vhi 34816 | vlo 44032
    __nv_bfloat16* qhi = sm;
    __nv_bfloat16* qlo = sm + 8704;
    __nv_bfloat16* khi = sm + 17408;
    __nv_bfloat16* klo = sm + 26112;
    __nv_bfloat16* vhi = sm + 34816;
    __nv_bfloat16* vlo = sm + 44032;
    float* srpb = reinterpret_cast<float*>(sm + 53248);

    const int tid = threadIdx.x;
    const int bt = blockIdx.x >> 1;
    const int hg = blockIdx.x & 1;          // head group: heads hg*4 .. hg*4+3
    const int b = bt >> 1;

    const float* qsrc = g_q + (size_t)b * (64 * 256) + hg * 128;
    const float* kvsrc = g_kv + (size_t)bt * (64 * 512) + hg * 128;

    // ---- stage q slice (64 x 128) ----
    #pragma unroll
    for (int u = 0; u < 8; u++) {
        int f = tid + u * 256;
        int r = f >> 5;
        int c = (f & 31) << 2;
        float4 v = *reinterpret_cast<const float4*>(qsrc + r * 256 + c);
        split_store(v.x, v.y, qhi + r * 136 + c, qlo + r * 136 + c);
        split_store(v.z, v.w, qhi + r * 136 + c + 2, qlo + r * 136 + c + 2);
    }
    // ---- stage k slice (64 x 128) ----
    #pragma unroll
    for (int u = 0; u < 8; u++) {
        int f = tid + u * 256;
        int r = f >> 5;
        int c = (f & 31) << 2;
        float4 v = *reinterpret_cast<const float4*>(kvsrc + r * 512 + c);
        split_store(v.x, v.y, khi + r * 136 + c, klo + r * 136 + c);
        split_store(v.z, v.w, khi + r * 136 + c + 2, klo + r * 136 + c + 2);
    }
    // ---- stage v slice transposed (v_t[d_local][seq], d_local 0..127) ----
    #pragma unroll
    for (int u = 0; u < 8; u++) {
        int f = tid + u * 256;
        int r = f >> 5;
        int c = (f & 31) << 2;
        float4 v = *reinterpret_cast<const float4*>(kvsrc + r * 512 + 256 + c);
        float vals[4] = {v.x, v.y, v.z, v.w};
        #pragma unroll
        for (int j = 0; j < 4; j++) {
            __nv_bfloat16 hb = __float2bfloat16(vals[j]);
            vhi[(c + j) * 72 + r] = hb;
            vlo[(c + j) * 72 + r] = __float2bfloat16(vals[j] - __bfloat162float(hb));
        }
    }
    for (int i = tid; i < 1800; i += 256) srpb[i] = rpb[i];
    __syncthreads();

    const int warp = tid >> 5, lane = tid & 31;
    const int hl = warp >> 1;               // local head 0..3
    const int h = hg * 4 + hl;              // global head
    const int half = warp & 1;
    const int g = lane >> 2, tc = lane & 3;
    const int r0 = half * 32;

    // ---- S = q @ k^T (32 x 64) ----
    float S[2][8][4];
    #pragma unroll
    for (int i = 0; i < 2; i++)
        #pragma unroll
        for (int j = 0; j < 8; j++)
            #pragma unroll
            for (int e = 0; e < 4; e++) S[i][j][e] = 0.f;

    #pragma unroll
    for (int kk = 0; kk < 2; kk++) {
        const int kc = hl * 32 + kk * 16 + tc * 2;
        uint ah[2][4], al[2][4];
        #pragma unroll
        for (int mi = 0; mi < 2; mi++) {
            int row = r0 + mi * 16 + g;
            ah[mi][0] = lds_u32(qhi + row * 136 + kc);
            ah[mi][1] = lds_u32(qhi + (row + 8) * 136 + kc);
            ah[mi][2] = lds_u32(qhi + row * 136 + kc + 8);
            ah[mi][3] = lds_u32(qhi + (row + 8) * 136 + kc + 8);
            al[mi][0] = lds_u32(qlo + row * 136 + kc);
            al[mi][1] = lds_u32(qlo + (row + 8) * 136 + kc);
            al[mi][2] = lds_u32(qlo + row * 136 + kc + 8);
            al[mi][3] = lds_u32(qlo + (row + 8) * 136 + kc + 8);
        }
        #pragma unroll
        for (int nj = 0; nj < 8; nj++) {
            int n = nj * 8 + g;
            uint bh[2], bl[2];
            bh[0] = lds_u32(khi + n * 136 + kc);
            bh[1] = lds_u32(khi + n * 136 + kc + 8);
            bl[0] = lds_u32(klo + n * 136 + kc);
            bl[1] = lds_u32(klo + n * 136 + kc + 8);
            #pragma unroll
            for (int mi = 0; mi < 2; mi++) {
                mma16816(S[mi][nj], ah[mi], bh);
                mma16816(S[mi][nj], al[mi], bh);
                mma16816(S[mi][nj], ah[mi], bl);
            }
        }
    }

    // ---- scale + bias + softmax (fp32) ----
    const float scale = 0.17677669529663687f;
    #pragma unroll
    for (int mi = 0; mi < 2; mi++) {
        #pragma unroll
        for (int p = 0; p < 2; p++) {
            int row = r0 + mi * 16 + g + p * 8;
            int pi = row >> 3, pj = row & 7;
            float mx = -1e30f;
            #pragma unroll
            for (int nj = 0; nj < 8; nj++) {
                #pragma unroll
                for (int e = 0; e < 2; e++) {
                    int col = nj * 8 + tc * 2 + e;
                    int qi = col >> 3, qj = col & 7;
                    int rel = (pi - qi + 7) * 15 + (pj - qj + 7);
                    float s = S[mi][nj][p * 2 + e] * scale + srpb[rel * 8 + h];
                    S[mi][nj][p * 2 + e] = s;
                    mx = fmaxf(mx, s);
                }
            }
            mx = fmaxf(mx, __shfl_xor_sync(0xffffffffu, mx, 1));
            mx = fmaxf(mx, __shfl_xor_sync(0xffffffffu, mx, 2));
            float sum = 0.f;
            #pragma unroll
            for (int nj = 0; nj < 8; nj++) {
                #pragma unroll
                for (int e = 0; e < 2; e++) {
                    float pe = __expf(S[mi][nj][p * 2 + e] - mx);
                    S[mi][nj][p * 2 + e] = pe;
                    sum += pe;
                }
            }
            sum += __shfl_xor_sync(0xffffffffu, sum, 1);
            sum += __shfl_xor_sync(0xffffffffu, sum, 2);
            float inv = 1.f / sum;
            #pragma unroll
            for (int nj = 0; nj < 8; nj++) {
                S[mi][nj][p * 2 + 0] *= inv;
                S[mi][nj][p * 2 + 1] *= inv;
            }
        }
    }

    // ---- pre-pack all of P to bf16 hi/lo (S dies; bounds register pressure) ----
    uint phi[2][8][2], plo[2][8][2];
    #pragma unroll
    for (int mi = 0; mi < 2; mi++)
        #pragma unroll
        for (int nj = 0; nj < 8; nj++) {
            packsplit(S[mi][nj][0], S[mi][nj][1], phi[mi][nj][0], plo[mi][nj][0]);
            packsplit(S[mi][nj][2], S[mi][nj][3], phi[mi][nj][1], plo[mi][nj][1]);
        }

    // ---- O = P @ v ----
    float O[2][4][4];
    #pragma unroll
    for (int i = 0; i < 2; i++)
        #pragma unroll
        for (int j = 0; j < 4; j++)
            #pragma unroll
            for (int e = 0; e < 4; e++) O[i][j][e] = 0.f;

    #pragma unroll
    for (int t = 0; t < 4; t++) {
        const int kb = t * 16 + tc * 2;
        #pragma unroll
        for (int jn = 0; jn < 4; jn++) {
            int d = hl * 32 + jn * 8 + g;
            uint bh[2], bl[2];
            bh[0] = lds_u32(vhi + d * 72 + kb);
            bh[1] = lds_u32(vhi + d * 72 + kb + 8);
            bl[0] = lds_u32(vlo + d * 72 + kb);
            bl[1] = lds_u32(vlo + d * 72 + kb + 8);
            #pragma unroll
            for (int mi = 0; mi < 2; mi++) {
                uint pa[4] = {phi[mi][2 * t][0], phi[mi][2 * t][1],
                              phi[mi][2 * t + 1][0], phi[mi][2 * t + 1][1]};
                uint la[4] = {plo[mi][2 * t][0], plo[mi][2 * t][1],
                              plo[mi][2 * t + 1][0], plo[mi][2 * t + 1][1]};
                mma16816(O[mi][jn], pa, bh);
                mma16816(O[mi][jn], la, bh);
                mma16816(O[mi][jn], pa, bl);
            }
        }
    }

    // ---- write O merged-head ----
    float* dst = g_att + (size_t)bt * (64 * 256);
    #pragma unroll
    for (int mi = 0; mi < 2; mi++) {
        #pragma unroll
        for (int jn = 0; jn < 4; jn++) {
            int row = r0 + mi * 16 + g;
            int col = h * 32 + jn * 8 + tc * 2;
            *reinterpret_cast<float2*>(dst + row * 256 + col) =
                make_float2(O[mi][jn][0], O[mi][jn][1]);
            *reinterpret_cast<float2*>(dst + (row + 8) * 256 + col) =
                make_float2(O[mi][jn][2], O[mi][jn][3]);
        }
    }
}

// =============================================================================
extern "C" void kernel_launch(void* const* d_in, const int* in_sizes, int n_in,
                              void* d_out, int out_size)
{
    const float* x      = (const float*)d_in[0];
    const float* memory = (const float*)d_in[1];
    const float* q_w    = (const float*)d_in[2];
    const float* q_b    = (const float*)d_in[3];
    const float* kv_w   = (const float*)d_in[4];
    const float* kv_b   = (const float*)d_in[5];
    const float* proj_w = (const float*)d_in[6];
    const float* proj_b = (const float*)d_in[7];
    const float* rpb    = (const float*)d_in[8];
    float* out = (float*)d_out;

    float *qbuf = nullptr, *kvbuf = nullptr, *attbuf = nullptr;
    cudaGetSymbolAddress((void**)&qbuf, g_q);
    cudaGetSymbolAddress((void**)&kvbuf, g_kv);
    cudaGetSymbolAddress((void**)&attbuf, g_att);

    cudaFuncSetAttribute(gemm_kernel,
                         cudaFuncAttributeMaxDynamicSharedMemorySize, 122880);
    cudaFuncSetAttribute(attn_kernel,
                         cudaFuncAttributeMaxDynamicSharedMemorySize, 113696);

    // q projection: (2048*64, 256) @ (256, 256)^T
    gemm_kernel<<<dim3(1, 1024), 512, 122880>>>(x, q_w, q_b, qbuf, 256);
    // kv projection: (4096*64, 256) @ (512, 256)^T
    gemm_kernel<<<dim3(2, 2048), 512, 122880>>>(memory, kv_w, kv_b, kvbuf, 512);
    // fused attention: 2 CTAs (4 heads each) per (b, t)
    attn_kernel<<<8192, 256, 113696>>>(rpb);
    // output projection: (4096*64, 256) @ (256, 256)^T
    gemm_kernel<<<dim3(1, 2048), 512, 122880>>>(attbuf, proj_w, proj_b, out, 256);
}

// round 5
// speedup vs baseline: 1.2491x; 1.2491x over previous
#include <cuda_runtime.h>
#include <cuda_bf16.h>
#include <cuda_fp16.h>

typedef unsigned int uint;

// ---------------- scratch (device globals; no allocs allowed) ----------------
__device__ float g_q[2048L * 64 * 256];    // 128 MB : q projection
__device__ float g_kv[4096L * 64 * 512];   // 512 MB : kv projection
__device__ float g_att[4096L * 64 * 256];  // 256 MB : attention output (pre-proj)

#define DEV_INLINE __device__ __forceinline__

// fp16 mma (GEMMs)
DEV_INLINE void mma16816f16(float* d, const uint* a, const uint* b) {
    asm volatile(
        "mma.sync.aligned.m16n8k16.row.col.f32.f16.f16.f32 "
        "{%0,%1,%2,%3}, {%4,%5,%6,%7}, {%8,%9}, {%0,%1,%2,%3};\n"
        : "+f"(d[0]), "+f"(d[1]), "+f"(d[2]), "+f"(d[3])
        : "r"(a[0]), "r"(a[1]), "r"(a[2]), "r"(a[3]), "r"(b[0]), "r"(b[1]));
}

// bf16 mma (attention)
DEV_INLINE void mma16816(float* d, const uint* a, const uint* b) {
    asm volatile(
        "mma.sync.aligned.m16n8k16.row.col.f32.bf16.bf16.f32 "
        "{%0,%1,%2,%3}, {%4,%5,%6,%7}, {%8,%9}, {%0,%1,%2,%3};\n"
        : "+f"(d[0]), "+f"(d[1]), "+f"(d[2]), "+f"(d[3])
        : "r"(a[0]), "r"(a[1]), "r"(a[2]), "r"(a[3]), "r"(b[0]), "r"(b[1]));
}

DEV_INLINE uint lds_u32(const void* p) {
    return *reinterpret_cast<const uint*>(p);
}

// fp32 pair -> fp16 hi + fp16 residual lo, stored to smem
DEV_INLINE void split_store_h(float x, float y, __half* hi_p, __half* lo_p) {
    __half2 h = __floats2half2_rn(x, y);
    __half2 l = __floats2half2_rn(x - __half2float(__low2half(h)),
                                  y - __half2float(__high2half(h)));
    *reinterpret_cast<__half2*>(hi_p) = h;
    *reinterpret_cast<__half2*>(lo_p) = l;
}

// fp32 pair -> bf16 hi + bf16 residual lo (attention staging)
DEV_INLINE void split_store(float x, float y, __nv_bfloat16* hi_p, __nv_bfloat16* lo_p) {
    __nv_bfloat162 h = __floats2bfloat162_rn(x, y);
    __nv_bfloat162 l = __floats2bfloat162_rn(x - __bfloat162float(h.x),
                                             y - __bfloat162float(h.y));
    *reinterpret_cast<__nv_bfloat162*>(hi_p) = h;
    *reinterpret_cast<__nv_bfloat162*>(lo_p) = l;
}

DEV_INLINE void packsplit(float x, float y, uint& hi, uint& lo) {
    __nv_bfloat162 h = __floats2bfloat162_rn(x, y);
    __nv_bfloat162 l = __floats2bfloat162_rn(x - __bfloat162float(h.x),
                                             y - __bfloat162float(h.y));
    hi = *reinterpret_cast<uint*>(&h);
    lo = *reinterpret_cast<uint*>(&l);
}

// =============================================================================
// GEMM: C[M,N] = A[M,256] @ B[N,256]^T + bias[N]   (fp16x2: (Ahi+Alo)@Bhi)
// R1-proven structure: 256 threads (8 warps, 4m x 2n), BM=128, BN=128, BK=32,
// double-buffered. Per k16 group: 2 MMAs (hi*bh, lo*bh).
// Stage: Ahi 128x40 | Alo 128x40 | Bhi 128x40 = 15360 half = 30720 B; x2 stages.
// =============================================================================
__global__ __launch_bounds__(256, 1) void gemm_kernel(
    const float* __restrict__ A, const float* __restrict__ B,
    const float* __restrict__ bias, float* __restrict__ C, int N)
{
    constexpr int K = 256;
    constexpr int LDT = 40;        // smem row stride in half (32 + 8 pad)
    constexpr int STG = 15360;     // half elements per stage
    extern __shared__ __half smh[];

    const int tid = threadIdx.x;
    const int m0 = blockIdx.y * 128;
    const int n0 = blockIdx.x * 128;

    auto load_stage = [&](int k0, __half* st) {
        #pragma unroll
        for (int u = 0; u < 4; u++) {                    // A: 128x32 = 1024 float4
            int f = tid + u * 256;
            int r = f >> 3;
            int c = (f & 7) << 2;
            float4 v = *reinterpret_cast<const float4*>(A + (size_t)(m0 + r) * K + k0 + c);
            __half* hp = st + r * LDT + c;
            __half* lp = st + 5120 + r * LDT + c;
            split_store_h(v.x, v.y, hp, lp);
            split_store_h(v.z, v.w, hp + 2, lp + 2);
        }
        #pragma unroll
        for (int u = 0; u < 4; u++) {                    // B: 128x32, hi only
            int f = tid + u * 256;
            int r = f >> 3;
            int c = (f & 7) << 2;
            float4 v = *reinterpret_cast<const float4*>(B + (size_t)(n0 + r) * K + k0 + c);
            __half* hp = st + 10240 + r * LDT + c;
            *reinterpret_cast<__half2*>(hp) = __floats2half2_rn(v.x, v.y);
            *reinterpret_cast<__half2*>(hp + 2) = __floats2half2_rn(v.z, v.w);
        }
    };

    const int warp = tid >> 5, lane = tid & 31;
    const int wm = warp & 3, wn = warp >> 2;
    const int g = lane >> 2, tc = lane & 3;

    float acc[2][8][4];
    #pragma unroll
    for (int i = 0; i < 2; i++)
        #pragma unroll
        for (int j = 0; j < 8; j++)
            #pragma unroll
            for (int e = 0; e < 4; e++) acc[i][j][e] = 0.f;

    load_stage(0, smh);
    __syncthreads();

    #pragma unroll
    for (int kt = 0; kt < 8; kt++) {
        if (kt < 7) load_stage((kt + 1) * 32, smh + ((kt + 1) & 1) * STG);

        const __half* st = smh + (kt & 1) * STG;
        const __half* Ah = st;
        const __half* Al = st + 5120;
        const __half* Bh = st + 10240;

        #pragma unroll
        for (int kk = 0; kk < 2; kk++) {
            const int kc = kk * 16 + tc * 2;
            uint ah[2][4], al[2][4];
            #pragma unroll
            for (int mi = 0; mi < 2; mi++) {
                int row = wm * 32 + mi * 16 + g;
                ah[mi][0] = lds_u32(Ah + row * LDT + kc);
                ah[mi][1] = lds_u32(Ah + (row + 8) * LDT + kc);
                ah[mi][2] = lds_u32(Ah + row * LDT + kc + 8);
                ah[mi][3] = lds_u32(Ah + (row + 8) * LDT + kc + 8);
                al[mi][0] = lds_u32(Al + row * LDT + kc);
                al[mi][1] = lds_u32(Al + (row + 8) * LDT + kc);
                al[mi][2] = lds_u32(Al + row * LDT + kc + 8);
                al[mi][3] = lds_u32(Al + (row + 8) * LDT + kc + 8);
            }
            #pragma unroll
            for (int nj = 0; nj < 8; nj++) {
                int n = wn * 64 + nj * 8 + g;
                uint bh[2];
                bh[0] = lds_u32(Bh + n * LDT + kc);
                bh[1] = lds_u32(Bh + n * LDT + kc + 8);
                #pragma unroll
                for (int mi = 0; mi < 2; mi++) {
                    mma16816f16(acc[mi][nj], ah[mi], bh);
                    mma16816f16(acc[mi][nj], al[mi], bh);
                }
            }
        }
        __syncthreads();
    }

    #pragma unroll
    for (int mi = 0; mi < 2; mi++) {
        #pragma unroll
        for (int nj = 0; nj < 8; nj++) {
            int row = m0 + wm * 32 + mi * 16 + g;
            int col = n0 + wn * 64 + nj * 8 + tc * 2;
            float b0 = __ldg(bias + col), b1 = __ldg(bias + col + 1);
            *reinterpret_cast<float2*>(C + (size_t)row * N + col) =
                make_float2(acc[mi][nj][0] + b0, acc[mi][nj][1] + b1);
            *reinterpret_cast<float2*>(C + (size_t)(row + 8) * N + col) =
                make_float2(acc[mi][nj][2] + b0, acc[mi][nj][3] + b1);
        }
    }
}

// =============================================================================
// Fused attention: one CTA per (bt, head-group of 4). 256 threads = 8 warps
// = 2 warps/head. smem ~113.7 KB -> 2 CTAs/SM. bf16x3 (unchanged, known good).
// =============================================================================
__global__ __launch_bounds__(256, 2) void attn_kernel(const float* __restrict__ rpb)
{
    extern __shared__ __nv_bfloat16 sm[];
    __nv_bfloat16* qhi = sm;
    __nv_bfloat16* qlo = sm + 8704;
    __nv_bfloat16* khi = sm + 17408;
    __nv_bfloat16* klo = sm + 26112;
    __nv_bfloat16* vhi = sm + 34816;
    __nv_bfloat16* vlo = sm + 44032;
    float* srpb = reinterpret_cast<float*>(sm + 53248);

    const int tid = threadIdx.x;
    const int bt = blockIdx.x >> 1;
    const int hg = blockIdx.x & 1;
    const int b = bt >> 1;

    const float* qsrc = g_q + (size_t)b * (64 * 256) + hg * 128;
    const float* kvsrc = g_kv + (size_t)bt * (64 * 512) + hg * 128;

    #pragma unroll
    for (int u = 0; u < 8; u++) {
        int f = tid + u * 256;
        int r = f >> 5;
        int c = (f & 31) << 2;
        float4 v = *reinterpret_cast<const float4*>(qsrc + r * 256 + c);
        split_store(v.x, v.y, qhi + r * 136 + c, qlo + r * 136 + c);
        split_store(v.z, v.w, qhi + r * 136 + c + 2, qlo + r * 136 + c + 2);
    }
    #pragma unroll
    for (int u = 0; u < 8; u++) {
        int f = tid + u * 256;
        int r = f >> 5;
        int c = (f & 31) << 2;
        float4 v = *reinterpret_cast<const float4*>(kvsrc + r * 512 + c);
        split_store(v.x, v.y, khi + r * 136 + c, klo + r * 136 + c);
        split_store(v.z, v.w, khi + r * 136 + c + 2, klo + r * 136 + c + 2);
    }
    #pragma unroll
    for (int u = 0; u < 8; u++) {
        int f = tid + u * 256;
        int r = f >> 5;
        int c = (f & 31) << 2;
        float4 v = *reinterpret_cast<const float4*>(kvsrc + r * 512 + 256 + c);
        float vals[4] = {v.x, v.y, v.z, v.w};
        #pragma unroll
        for (int j = 0; j < 4; j++) {
            __nv_bfloat16 hb = __float2bfloat16(vals[j]);
            vhi[(c + j) * 72 + r] = hb;
            vlo[(c + j) * 72 + r] = __float2bfloat16(vals[j] - __bfloat162float(hb));
        }
    }
    for (int i = tid; i < 1800; i += 256) srpb[i] = rpb[i];
    __syncthreads();

    const int warp = tid >> 5, lane = tid & 31;
    const int hl = warp >> 1;
    const int h = hg * 4 + hl;
    const int half = warp & 1;
    const int g = lane >> 2, tc = lane & 3;
    const int r0 = half * 32;

    float S[2][8][4];
    #pragma unroll
    for (int i = 0; i < 2; i++)
        #pragma unroll
        for (int j = 0; j < 8; j++)
            #pragma unroll
            for (int e = 0; e < 4; e++) S[i][j][e] = 0.f;

    #pragma unroll
    for (int kk = 0; kk < 2; kk++) {
        const int kc = hl * 32 + kk * 16 + tc * 2;
        uint ah[2][4], al[2][4];
        #pragma unroll
        for (int mi = 0; mi < 2; mi++) {
            int row = r0 + mi * 16 + g;
            ah[mi][0] = lds_u32(qhi + row * 136 + kc);
            ah[mi][1] = lds_u32(qhi + (row + 8) * 136 + kc);
            ah[mi][2] = lds_u32(qhi + row * 136 + kc + 8);
            ah[mi][3] = lds_u32(qhi + (row + 8) * 136 + kc + 8);
            al[mi][0] = lds_u32(qlo + row * 136 + kc);
            al[mi][1] = lds_u32(qlo + (row + 8) * 136 + kc);
            al[mi][2] = lds_u32(qlo + row * 136 + kc + 8);
            al[mi][3] = lds_u32(qlo + (row + 8) * 136 + kc + 8);
        }
        #pragma unroll
        for (int nj = 0; nj < 8; nj++) {
            int n = nj * 8 + g;
            uint bh[2], bl[2];
            bh[0] = lds_u32(khi + n * 136 + kc);
            bh[1] = lds_u32(khi + n * 136 + kc + 8);
            bl[0] = lds_u32(klo + n * 136 + kc);
            bl[1] = lds_u32(klo + n * 136 + kc + 8);
            #pragma unroll
            for (int mi = 0; mi < 2; mi++) {
                mma16816(S[mi][nj], ah[mi], bh);
                mma16816(S[mi][nj], al[mi], bh);
                mma16816(S[mi][nj], ah[mi], bl);
            }
        }
    }

    const float scale = 0.17677669529663687f;
    #pragma unroll
    for (int mi = 0; mi < 2; mi++) {
        #pragma unroll
        for (int p = 0; p < 2; p++) {
            int row = r0 + mi * 16 + g + p * 8;
            int pi = row >> 3, pj = row & 7;
            float mx = -1e30f;
            #pragma unroll
            for (int nj = 0; nj < 8; nj++) {
                #pragma unroll
                for (int e = 0; e < 2; e++) {
                    int col = nj * 8 + tc * 2 + e;
                    int qi = col >> 3, qj = col & 7;
                    int rel = (pi - qi + 7) * 15 + (pj - qj + 7);
                    float s = S[mi][nj][p * 2 + e] * scale + srpb[rel * 8 + h];
                    S[mi][nj][p * 2 + e] = s;
                    mx = fmaxf(mx, s);
                }
            }
            mx = fmaxf(mx, __shfl_xor_sync(0xffffffffu, mx, 1));
            mx = fmaxf(mx, __shfl_xor_sync(0xffffffffu, mx, 2));
            float sum = 0.f;
            #pragma unroll
            for (int nj = 0; nj < 8; nj++) {
                #pragma unroll
                for (int e = 0; e < 2; e++) {
                    float pe = __expf(S[mi][nj][p * 2 + e] - mx);
                    S[mi][nj][p * 2 + e] = pe;
                    sum += pe;
                }
            }
            sum += __shfl_xor_sync(0xffffffffu, sum, 1);
            sum += __shfl_xor_sync(0xffffffffu, sum, 2);
            float inv = 1.f / sum;
            #pragma unroll
            for (int nj = 0; nj < 8; nj++) {
                S[mi][nj][p * 2 + 0] *= inv;
                S[mi][nj][p * 2 + 1] *= inv;
            }
        }
    }

    uint phi[2][8][2], plo[2][8][2];
    #pragma unroll
    for (int mi = 0; mi < 2; mi++)
        #pragma unroll
        for (int nj = 0; nj < 8; nj++) {
            packsplit(S[mi][nj][0], S[mi][nj][1], phi[mi][nj][0], plo[mi][nj][0]);
            packsplit(S[mi][nj][2], S[mi][nj][3], phi[mi][nj][1], plo[mi][nj][1]);
        }

    float O[2][4][4];
    #pragma unroll
    for (int i = 0; i < 2; i++)
        #pragma unroll
        for (int j = 0; j < 4; j++)
            #pragma unroll
            for (int e = 0; e < 4; e++) O[i][j][e] = 0.f;

    #pragma unroll
    for (int t = 0; t < 4; t++) {
        const int kb = t * 16 + tc * 2;
        #pragma unroll
        for (int jn = 0; jn < 4; jn++) {
            int d = hl * 32 + jn * 8 + g;
            uint bh[2], bl[2];
            bh[0] = lds_u32(vhi + d * 72 + kb);
            bh[1] = lds_u32(vhi + d * 72 + kb + 8);
            bl[0] = lds_u32(vlo + d * 72 + kb);
            bl[1] = lds_u32(vlo + d * 72 + kb + 8);
            #pragma unroll
            for (int mi = 0; mi < 2; mi++) {
                uint pa[4] = {phi[mi][2 * t][0], phi[mi][2 * t][1],
                              phi[mi][2 * t + 1][0], phi[mi][2 * t + 1][1]};
                uint la[4] = {plo[mi][2 * t][0], plo[mi][2 * t][1],
                              plo[mi][2 * t + 1][0], plo[mi][2 * t + 1][1]};
                mma16816(O[mi][jn], pa, bh);
                mma16816(O[mi][jn], la, bh);
                mma16816(O[mi][jn], pa, bl);
            }
        }
    }

    float* dst = g_att + (size_t)bt * (64 * 256);
    #pragma unroll
    for (int mi = 0; mi < 2; mi++) {
        #pragma unroll
        for (int jn = 0; jn < 4; jn++) {
            int row = r0 + mi * 16 + g;
            int col = h * 32 + jn * 8 + tc * 2;
            *reinterpret_cast<float2*>(dst + row * 256 + col) =
                make_float2(O[mi][jn][0], O[mi][jn][1]);
            *reinterpret_cast<float2*>(dst + (row + 8) * 256 + col) =
                make_float2(O[mi][jn][2], O[mi][jn][3]);
        }
    }
}

// =============================================================================
extern "C" void kernel_launch(void* const* d_in, const int* in_sizes, int n_in,
                              void* d_out, int out_size)
{
    const float* x      = (const float*)d_in[0];
    const float* memory = (const float*)d_in[1];
    const float* q_w    = (const float*)d_in[2];
    const float* q_b    = (const float*)d_in[3];
    const float* kv_w   = (const float*)d_in[4];
    const float* kv_b   = (const float*)d_in[5];
    const float* proj_w = (const float*)d_in[6];
    const float* proj_b = (const float*)d_in[7];
    const float* rpb    = (const float*)d_in[8];
    float* out = (float*)d_out;

    float *qbuf = nullptr, *kvbuf = nullptr, *attbuf = nullptr;
    cudaGetSymbolAddress((void**)&qbuf, g_q);
    cudaGetSymbolAddress((void**)&kvbuf, g_kv);
    cudaGetSymbolAddress((void**)&attbuf, g_att);

    cudaFuncSetAttribute(gemm_kernel,
                         cudaFuncAttributeMaxDynamicSharedMemorySize, 61440);
    cudaFuncSetAttribute(attn_kernel,
                         cudaFuncAttributeMaxDynamicSharedMemorySize, 113696);

    // q projection: (2048*64, 256) @ (256, 256)^T
    gemm_kernel<<<dim3(2, 1024), 256, 61440>>>(x, q_w, q_b, qbuf, 256);
    // kv projection: (4096*64, 256) @ (512, 256)^T
    gemm_kernel<<<dim3(4, 2048), 256, 61440>>>(memory, kv_w, kv_b, kvbuf, 512);
    // fused attention: 2 CTAs (4 heads each) per (b, t)
    attn_kernel<<<8192, 256, 113696>>>(rpb);
    // output projection: (4096*64, 256) @ (256, 256)^T
    gemm_kernel<<<dim3(2, 2048), 256, 61440>>>(attbuf, proj_w, proj_b, out, 256);
}

// round 6
// speedup vs baseline: 1.3770x; 1.1025x over previous
#include <cuda_runtime.h>
#include <cuda_bf16.h>
#include <cuda_fp16.h>

typedef unsigned int uint;

// ---------------- scratch (device globals; no allocs allowed) ----------------
__device__ float g_q[2048L * 64 * 256];    // 128 MB : q projection
__device__ float g_kv[4096L * 64 * 512];   // 512 MB : kv projection
__device__ float g_att[4096L * 64 * 256];  // 256 MB : attention output (pre-proj)

#define DEV_INLINE __device__ __forceinline__

DEV_INLINE void mma16816f16(float* d, const uint* a, const uint* b) {
    asm volatile(
        "mma.sync.aligned.m16n8k16.row.col.f32.f16.f16.f32 "
        "{%0,%1,%2,%3}, {%4,%5,%6,%7}, {%8,%9}, {%0,%1,%2,%3};\n"
        : "+f"(d[0]), "+f"(d[1]), "+f"(d[2]), "+f"(d[3])
        : "r"(a[0]), "r"(a[1]), "r"(a[2]), "r"(a[3]), "r"(b[0]), "r"(b[1]));
}

DEV_INLINE uint lds_u32(const void* p) {
    return *reinterpret_cast<const uint*>(p);
}

// fp32 pair -> fp16 hi + fp16 residual lo, stored to smem
DEV_INLINE void split_store_h(float x, float y, __half* hi_p, __half* lo_p) {
    __half2 h = __floats2half2_rn(x, y);
    __half2 l = __floats2half2_rn(x - __half2float(__low2half(h)),
                                  y - __half2float(__high2half(h)));
    *reinterpret_cast<__half2*>(hi_p) = h;
    *reinterpret_cast<__half2*>(lo_p) = l;
}

// fp32 pair -> packed fp16x2 hi + residual lo registers
DEV_INLINE void packsplit_h(float x, float y, uint& hi, uint& lo) {
    __half2 h = __floats2half2_rn(x, y);
    __half2 l = __floats2half2_rn(x - __half2float(__low2half(h)),
                                  y - __half2float(__high2half(h)));
    hi = *reinterpret_cast<uint*>(&h);
    lo = *reinterpret_cast<uint*>(&l);
}

// =============================================================================
// GEMM: C[M,N] = A[M,256] @ B[N,256]^T + bias[N]   (fp16x2: (Ahi+Alo)@Bhi)
// 256 threads (8 warps, 4m x 2n), BM=128, BN=64, BK=32, double-buffered.
// Warp tile 32x32 -> acc 32 regs -> 2 CTAs/SM (occupancy to hide load latency).
// Stage: Ahi 128x40 | Alo 128x40 | Bhi 64x40 = 12800 half = 25600 B; x2 stages.
// =============================================================================
__global__ __launch_bounds__(256, 2) void gemm_kernel(
    const float* __restrict__ A, const float* __restrict__ B,
    const float* __restrict__ bias, float* __restrict__ C, int N)
{
    constexpr int K = 256;
    constexpr int LDT = 40;        // smem row stride in half (32 + 8 pad)
    constexpr int STG = 12800;     // half elements per stage
    extern __shared__ __half smh[];

    const int tid = threadIdx.x;
    const int m0 = blockIdx.y * 128;
    const int n0 = blockIdx.x * 64;

    auto load_stage = [&](int k0, __half* st) {
        #pragma unroll
        for (int u = 0; u < 4; u++) {                    // A: 128x32 = 1024 float4
            int f = tid + u * 256;
            int r = f >> 3;
            int c = (f & 7) << 2;
            float4 v = *reinterpret_cast<const float4*>(A + (size_t)(m0 + r) * K + k0 + c);
            __half* hp = st + r * LDT + c;
            __half* lp = st + 5120 + r * LDT + c;
            split_store_h(v.x, v.y, hp, lp);
            split_store_h(v.z, v.w, hp + 2, lp + 2);
        }
        #pragma unroll
        for (int u = 0; u < 2; u++) {                    // B: 64x32, hi only
            int f = tid + u * 256;
            int r = f >> 3;
            int c = (f & 7) << 2;
            float4 v = *reinterpret_cast<const float4*>(B + (size_t)(n0 + r) * K + k0 + c);
            __half* hp = st + 10240 + r * LDT + c;
            *reinterpret_cast<__half2*>(hp) = __floats2half2_rn(v.x, v.y);
            *reinterpret_cast<__half2*>(hp + 2) = __floats2half2_rn(v.z, v.w);
        }
    };

    const int warp = tid >> 5, lane = tid & 31;
    const int wm = warp & 3, wn = warp >> 2;
    const int g = lane >> 2, tc = lane & 3;

    float acc[2][4][4];
    #pragma unroll
    for (int i = 0; i < 2; i++)
        #pragma unroll
        for (int j = 0; j < 4; j++)
            #pragma unroll
            for (int e = 0; e < 4; e++) acc[i][j][e] = 0.f;

    load_stage(0, smh);
    __syncthreads();

    #pragma unroll
    for (int kt = 0; kt < 8; kt++) {
        if (kt < 7) load_stage((kt + 1) * 32, smh + ((kt + 1) & 1) * STG);

        const __half* st = smh + (kt & 1) * STG;
        const __half* Ah = st;
        const __half* Al = st + 5120;
        const __half* Bh = st + 10240;

        #pragma unroll
        for (int kk = 0; kk < 2; kk++) {
            const int kc = kk * 16 + tc * 2;
            uint ah[2][4], al[2][4];
            #pragma unroll
            for (int mi = 0; mi < 2; mi++) {
                int row = wm * 32 + mi * 16 + g;
                ah[mi][0] = lds_u32(Ah + row * LDT + kc);
                ah[mi][1] = lds_u32(Ah + (row + 8) * LDT + kc);
                ah[mi][2] = lds_u32(Ah + row * LDT + kc + 8);
                ah[mi][3] = lds_u32(Ah + (row + 8) * LDT + kc + 8);
                al[mi][0] = lds_u32(Al + row * LDT + kc);
                al[mi][1] = lds_u32(Al + (row + 8) * LDT + kc);
                al[mi][2] = lds_u32(Al + row * LDT + kc + 8);
                al[mi][3] = lds_u32(Al + (row + 8) * LDT + kc + 8);
            }
            #pragma unroll
            for (int nj = 0; nj < 4; nj++) {
                int n = wn * 32 + nj * 8 + g;
                uint bh[2];
                bh[0] = lds_u32(Bh + n * LDT + kc);
                bh[1] = lds_u32(Bh + n * LDT + kc + 8);
                #pragma unroll
                for (int mi = 0; mi < 2; mi++) {
                    mma16816f16(acc[mi][nj], ah[mi], bh);
                    mma16816f16(acc[mi][nj], al[mi], bh);
                }
            }
        }
        __syncthreads();
    }

    #pragma unroll
    for (int mi = 0; mi < 2; mi++) {
        #pragma unroll
        for (int nj = 0; nj < 4; nj++) {
            int row = m0 + wm * 32 + mi * 16 + g;
            int col = n0 + wn * 32 + nj * 8 + tc * 2;
            float b0 = __ldg(bias + col), b1 = __ldg(bias + col + 1);
            *reinterpret_cast<float2*>(C + (size_t)row * N + col) =
                make_float2(acc[mi][nj][0] + b0, acc[mi][nj][1] + b1);
            *reinterpret_cast<float2*>(C + (size_t)(row + 8) * N + col) =
                make_float2(acc[mi][nj][2] + b0, acc[mi][nj][3] + b1);
        }
    }
}

// =============================================================================
// Fused attention (fp16x2): one CTA per (bt, head-group of 4). 256 threads =
// 8 warps = 2 warps/head. S = (qh+ql)@kh ; O = (Ph+Pl)@Vh. fp32 softmax.
// smem: qhi|qlo 64x136, khi 64x136, vhi_t 128x72 (half) + rpb 1800 f32 = 77856B
// -> 2 CTAs/SM.
// =============================================================================
__global__ __launch_bounds__(256, 2) void attn_kernel(const float* __restrict__ rpb)
{
    extern __shared__ __half smq[];
    __half* qhi = smq;                    // 8704
    __half* qlo = smq + 8704;             // 8704
    __half* khi = smq + 17408;            // 8704
    __half* vhi = smq + 26112;            // 128 x 72 = 9216
    float* srpb = reinterpret_cast<float*>(smq + 35328);

    const int tid = threadIdx.x;
    const int bt = blockIdx.x >> 1;
    const int hg = blockIdx.x & 1;
    const int b = bt >> 1;

    const float* qsrc = g_q + (size_t)b * (64 * 256) + hg * 128;
    const float* kvsrc = g_kv + (size_t)bt * (64 * 512) + hg * 128;

    // ---- stage q slice (64 x 128), split hi/lo ----
    #pragma unroll
    for (int u = 0; u < 8; u++) {
        int f = tid + u * 256;
        int r = f >> 5;
        int c = (f & 31) << 2;
        float4 v = *reinterpret_cast<const float4*>(qsrc + r * 256 + c);
        split_store_h(v.x, v.y, qhi + r * 136 + c, qlo + r * 136 + c);
        split_store_h(v.z, v.w, qhi + r * 136 + c + 2, qlo + r * 136 + c + 2);
    }
    // ---- stage k slice (64 x 128), hi only ----
    #pragma unroll
    for (int u = 0; u < 8; u++) {
        int f = tid + u * 256;
        int r = f >> 5;
        int c = (f & 31) << 2;
        float4 v = *reinterpret_cast<const float4*>(kvsrc + r * 512 + c);
        __half* hp = khi + r * 136 + c;
        *reinterpret_cast<__half2*>(hp) = __floats2half2_rn(v.x, v.y);
        *reinterpret_cast<__half2*>(hp + 2) = __floats2half2_rn(v.z, v.w);
    }
    // ---- stage v slice transposed (v_t[d_local][seq]), hi only ----
    #pragma unroll
    for (int u = 0; u < 8; u++) {
        int f = tid + u * 256;
        int r = f >> 5;
        int c = (f & 31) << 2;
        float4 v = *reinterpret_cast<const float4*>(kvsrc + r * 512 + 256 + c);
        float vals[4] = {v.x, v.y, v.z, v.w};
        #pragma unroll
        for (int j = 0; j < 4; j++)
            vhi[(c + j) * 72 + r] = __float2half(vals[j]);
    }
    for (int i = tid; i < 1800; i += 256) srpb[i] = rpb[i];
    __syncthreads();

    const int warp = tid >> 5, lane = tid & 31;
    const int hl = warp >> 1;
    const int h = hg * 4 + hl;
    const int half = warp & 1;
    const int g = lane >> 2, tc = lane & 3;
    const int r0 = half * 32;

    // ---- S = (qh + ql) @ kh^T (32 x 64) ----
    float S[2][8][4];
    #pragma unroll
    for (int i = 0; i < 2; i++)
        #pragma unroll
        for (int j = 0; j < 8; j++)
            #pragma unroll
            for (int e = 0; e < 4; e++) S[i][j][e] = 0.f;

    #pragma unroll
    for (int kk = 0; kk < 2; kk++) {
        const int kc = hl * 32 + kk * 16 + tc * 2;
        uint ah[2][4], al[2][4];
        #pragma unroll
        for (int mi = 0; mi < 2; mi++) {
            int row = r0 + mi * 16 + g;
            ah[mi][0] = lds_u32(qhi + row * 136 + kc);
            ah[mi][1] = lds_u32(qhi + (row + 8) * 136 + kc);
            ah[mi][2] = lds_u32(qhi + row * 136 + kc + 8);
            ah[mi][3] = lds_u32(qhi + (row + 8) * 136 + kc + 8);
            al[mi][0] = lds_u32(qlo + row * 136 + kc);
            al[mi][1] = lds_u32(qlo + (row + 8) * 136 + kc);
            al[mi][2] = lds_u32(qlo + row * 136 + kc + 8);
            al[mi][3] = lds_u32(qlo + (row + 8) * 136 + kc + 8);
        }
        #pragma unroll
        for (int nj = 0; nj < 8; nj++) {
            int n = nj * 8 + g;
            uint bh[2];
            bh[0] = lds_u32(khi + n * 136 + kc);
            bh[1] = lds_u32(khi + n * 136 + kc + 8);
            #pragma unroll
            for (int mi = 0; mi < 2; mi++) {
                mma16816f16(S[mi][nj], ah[mi], bh);
                mma16816f16(S[mi][nj], al[mi], bh);
            }
        }
    }

    // ---- scale + relative-position bias + softmax (fp32) ----
    const float scale = 0.17677669529663687f;
    #pragma unroll
    for (int mi = 0; mi < 2; mi++) {
        #pragma unroll
        for (int p = 0; p < 2; p++) {
            int row = r0 + mi * 16 + g + p * 8;
            int pi = row >> 3, pj = row & 7;
            float mx = -1e30f;
            #pragma unroll
            for (int nj = 0; nj < 8; nj++) {
                #pragma unroll
                for (int e = 0; e < 2; e++) {
                    int col = nj * 8 + tc * 2 + e;
                    int qi = col >> 3, qj = col & 7;
                    int rel = (pi - qi + 7) * 15 + (pj - qj + 7);
                    float s = S[mi][nj][p * 2 + e] * scale + srpb[rel * 8 + h];
                    S[mi][nj][p * 2 + e] = s;
                    mx = fmaxf(mx, s);
                }
            }
            mx = fmaxf(mx, __shfl_xor_sync(0xffffffffu, mx, 1));
            mx = fmaxf(mx, __shfl_xor_sync(0xffffffffu, mx, 2));
            float sum = 0.f;
            #pragma unroll
            for (int nj = 0; nj < 8; nj++) {
                #pragma unroll
                for (int e = 0; e < 2; e++) {
                    float pe = __expf(S[mi][nj][p * 2 + e] - mx);
                    S[mi][nj][p * 2 + e] = pe;
                    sum += pe;
                }
            }
            sum += __shfl_xor_sync(0xffffffffu, sum, 1);
            sum += __shfl_xor_sync(0xffffffffu, sum, 2);
            float inv = 1.f / sum;
            #pragma unroll
            for (int nj = 0; nj < 8; nj++) {
                S[mi][nj][p * 2 + 0] *= inv;
                S[mi][nj][p * 2 + 1] *= inv;
            }
        }
    }

    // ---- pack P to fp16 hi/lo (S dies) ----
    uint phi[2][8][2], plo[2][8][2];
    #pragma unroll
    for (int mi = 0; mi < 2; mi++)
        #pragma unroll
        for (int nj = 0; nj < 8; nj++) {
            packsplit_h(S[mi][nj][0], S[mi][nj][1], phi[mi][nj][0], plo[mi][nj][0]);
            packsplit_h(S[mi][nj][2], S[mi][nj][3], phi[mi][nj][1], plo[mi][nj][1]);
        }

    // ---- O = (Ph + Pl) @ Vh ----
    float O[2][4][4];
    #pragma unroll
    for (int i = 0; i < 2; i++)
        #pragma unroll
        for (int j = 0; j < 4; j++)
            #pragma unroll
            for (int e = 0; e < 4; e++) O[i][j][e] = 0.f;

    #pragma unroll
    for (int t = 0; t < 4; t++) {
        const int kb = t * 16 + tc * 2;
        #pragma unroll
        for (int jn = 0; jn < 4; jn++) {
            int d = hl * 32 + jn * 8 + g;
            uint bh[2];
            bh[0] = lds_u32(vhi + d * 72 + kb);
            bh[1] = lds_u32(vhi + d * 72 + kb + 8);
            #pragma unroll
            for (int mi = 0; mi < 2; mi++) {
                uint pa[4] = {phi[mi][2 * t][0], phi[mi][2 * t][1],
                              phi[mi][2 * t + 1][0], phi[mi][2 * t + 1][1]};
                uint la[4] = {plo[mi][2 * t][0], plo[mi][2 * t][1],
                              plo[mi][2 * t + 1][0], plo[mi][2 * t + 1][1]};
                mma16816f16(O[mi][jn], pa, bh);
                mma16816f16(O[mi][jn], la, bh);
            }
        }
    }

    // ---- write O merged-head ----
    float* dst = g_att + (size_t)bt * (64 * 256);
    #pragma unroll
    for (int mi = 0; mi < 2; mi++) {
        #pragma unroll
        for (int jn = 0; jn < 4; jn++) {
            int row = r0 + mi * 16 + g;
            int col = h * 32 + jn * 8 + tc * 2;
            *reinterpret_cast<float2*>(dst + row * 256 + col) =
                make_float2(O[mi][jn][0], O[mi][jn][1]);
            *reinterpret_cast<float2*>(dst + (row + 8) * 256 + col) =
                make_float2(O[mi][jn][2], O[mi][jn][3]);
        }
    }
}

// =============================================================================
extern "C" void kernel_launch(void* const* d_in, const int* in_sizes, int n_in,
                              void* d_out, int out_size)
{
    const float* x      = (const float*)d_in[0];
    const float* memory = (const float*)d_in[1];
    const float* q_w    = (const float*)d_in[2];
    const float* q_b    = (const float*)d_in[3];
    const float* kv_w   = (const float*)d_in[4];
    const float* kv_b   = (const float*)d_in[5];
    const float* proj_w = (const float*)d_in[6];
    const float* proj_b = (const float*)d_in[7];
    const float* rpb    = (const float*)d_in[8];
    float* out = (float*)d_out;

    float *qbuf = nullptr, *kvbuf = nullptr, *attbuf = nullptr;
    cudaGetSymbolAddress((void**)&qbuf, g_q);
    cudaGetSymbolAddress((void**)&kvbuf, g_kv);
    cudaGetSymbolAddress((void**)&attbuf, g_att);

    cudaFuncSetAttribute(gemm_kernel,
                         cudaFuncAttributeMaxDynamicSharedMemorySize, 51200);
    cudaFuncSetAttribute(attn_kernel,
                         cudaFuncAttributeMaxDynamicSharedMemorySize, 77856);

    // q projection: (2048*64, 256) @ (256, 256)^T
    gemm_kernel<<<dim3(4, 1024), 256, 51200>>>(x, q_w, q_b, qbuf, 256);
    // kv projection: (4096*64, 256) @ (512, 256)^T
    gemm_kernel<<<dim3(8, 2048), 256, 51200>>>(memory, kv_w, kv_b, kvbuf, 512);
    // fused attention: 2 CTAs (4 heads each) per (b, t)
    attn_kernel<<<8192, 256, 77856>>>(rpb);
    // output projection: (4096*64, 256) @ (256, 256)^T
    gemm_kernel<<<dim3(4, 2048), 256, 51200>>>(attbuf, proj_w, proj_b, out, 256);
}

// round 8
// speedup vs baseline: 1.5156x; 1.1006x over previous
#include <cuda_runtime.h>
#include <cuda_bf16.h>
#include <cuda_fp16.h>

typedef unsigned int uint;

// ---------------- scratch (device globals; no allocs allowed) ----------------
__device__ float g_q[2048L * 64 * 256];    // 128 MB : q projection
__device__ float g_kv[4096L * 64 * 512];   // 512 MB : kv projection
__device__ float g_att[4096L * 64 * 256];  // 256 MB : attention output (pre-proj)

#define DEV_INLINE __device__ __forceinline__

DEV_INLINE void mma16816f16(float* d, const uint* a, const uint* b) {
    asm volatile(
        "mma.sync.aligned.m16n8k16.row.col.f32.f16.f16.f32 "
        "{%0,%1,%2,%3}, {%4,%5,%6,%7}, {%8,%9}, {%0,%1,%2,%3};\n"
        : "+f"(d[0]), "+f"(d[1]), "+f"(d[2]), "+f"(d[3])
        : "r"(a[0]), "r"(a[1]), "r"(a[2]), "r"(a[3]), "r"(b[0]), "r"(b[1]));
}

DEV_INLINE uint lds_u32(const void* p) {
    return *reinterpret_cast<const uint*>(p);
}

// fp32 pair -> fp16 hi + fp16 residual lo, stored to smem
DEV_INLINE void split_store_h(float x, float y, __half* hi_p, __half* lo_p) {
    __half2 h = __floats2half2_rn(x, y);
    __half2 l = __floats2half2_rn(x - __half2float(__low2half(h)),
                                  y - __half2float(__high2half(h)));
    *reinterpret_cast<__half2*>(hi_p) = h;
    *reinterpret_cast<__half2*>(lo_p) = l;
}

// fp32 pair -> packed fp16x2 hi + residual lo registers
DEV_INLINE void packsplit_h(float x, float y, uint& hi, uint& lo) {
    __half2 h = __floats2half2_rn(x, y);
    __half2 l = __floats2half2_rn(x - __half2float(__low2half(h)),
                                  y - __half2float(__high2half(h)));
    hi = *reinterpret_cast<uint*>(&h);
    lo = *reinterpret_cast<uint*>(&l);
}

// =============================================================================
// GEMM: C[M,N] = A[M,256] @ B[N,256]^T + bias[N]   (fp16x2: (Ahi+Alo)@Bhi)
// 256 threads (8 warps, 4m x 2n), BM=128, BN=128, BK=32, warp tile 32x64.
// Software-pipelined: ldg(kt+2) -> MMA(kt) -> cvt+sts(kt+1) -> sync.
// Stage: Ahi 128x40 | Alo 128x40 | Bhi 128x40 = 15360 half = 30720 B; x2.
// =============================================================================
__global__ __launch_bounds__(256, 1) void gemm_kernel(
    const float* __restrict__ A, const float* __restrict__ B,
    const float* __restrict__ bias, float* __restrict__ C, int N)
{
    constexpr int K = 256;
    constexpr int LDT = 40;        // smem row stride in half (32 + 8 pad)
    constexpr int STG = 15360;     // half elements per stage
    extern __shared__ __half smh[];

    const int tid = threadIdx.x;
    const int m0 = blockIdx.y * 128;
    const int n0 = blockIdx.x * 128;

    const int lr = tid >> 3;             // load row 0..31 base (x4 over u)
    const int lc = (tid & 7) << 2;       // load col 0..28

    // two alternating register sets for in-flight stage data
    float4 va0[4], vb0[4], va1[4], vb1[4];

    auto ldg_stage = [&](int k0, float4 (&va)[4], float4 (&vb)[4]) {
        #pragma unroll
        for (int u = 0; u < 4; u++) {
            int r = lr + u * 32;
            va[u] = *reinterpret_cast<const float4*>(A + (size_t)(m0 + r) * K + k0 + lc);
            vb[u] = *reinterpret_cast<const float4*>(B + (size_t)(n0 + r) * K + k0 + lc);
        }
    };
    auto sts_stage = [&](__half* st, const float4 (&va)[4], const float4 (&vb)[4]) {
        #pragma unroll
        for (int u = 0; u < 4; u++) {
            int r = lr + u * 32;
            __half* hp = st + r * LDT + lc;
            __half* lp = st + 5120 + r * LDT + lc;
            split_store_h(va[u].x, va[u].y, hp, lp);
            split_store_h(va[u].z, va[u].w, hp + 2, lp + 2);
            __half* bp = st + 10240 + r * LDT + lc;
            *reinterpret_cast<__half2*>(bp) = __floats2half2_rn(vb[u].x, vb[u].y);
            *reinterpret_cast<__half2*>(bp + 2) = __floats2half2_rn(vb[u].z, vb[u].w);
        }
    };

    const int warp = tid >> 5, lane = tid & 31;
    const int wm = warp & 3, wn = warp >> 2;
    const int g = lane >> 2, tc = lane & 3;

    float acc[2][8][4];
    #pragma unroll
    for (int i = 0; i < 2; i++)
        #pragma unroll
        for (int j = 0; j < 8; j++)
            #pragma unroll
            for (int e = 0; e < 4; e++) acc[i][j][e] = 0.f;

    // prologue: stage0 in smem buf0; stage1 in reg set1
    ldg_stage(0, va0, vb0);
    sts_stage(smh, va0, vb0);
    ldg_stage(32, va1, vb1);
    __syncthreads();

    #pragma unroll
    for (int kt = 0; kt < 8; kt++) {
        // issue loads for stage kt+2 into the set freed last iteration
        if (kt < 6) {
            if ((kt & 1) == 0) ldg_stage((kt + 2) * 32, va0, vb0);
            else               ldg_stage((kt + 2) * 32, va1, vb1);
        }

        const __half* st = smh + (kt & 1) * STG;
        const __half* Ah = st;
        const __half* Al = st + 5120;
        const __half* Bh = st + 10240;

        #pragma unroll
        for (int kk = 0; kk < 2; kk++) {
            const int kc = kk * 16 + tc * 2;
            uint ah[2][4], al[2][4];
            #pragma unroll
            for (int mi = 0; mi < 2; mi++) {
                int row = wm * 32 + mi * 16 + g;
                ah[mi][0] = lds_u32(Ah + row * LDT + kc);
                ah[mi][1] = lds_u32(Ah + (row + 8) * LDT + kc);
                ah[mi][2] = lds_u32(Ah + row * LDT + kc + 8);
                ah[mi][3] = lds_u32(Ah + (row + 8) * LDT + kc + 8);
                al[mi][0] = lds_u32(Al + row * LDT + kc);
                al[mi][1] = lds_u32(Al + (row + 8) * LDT + kc);
                al[mi][2] = lds_u32(Al + row * LDT + kc + 8);
                al[mi][3] = lds_u32(Al + (row + 8) * LDT + kc + 8);
            }
            #pragma unroll
            for (int nj = 0; nj < 8; nj++) {
                int n = wn * 64 + nj * 8 + g;
                uint bh[2];
                bh[0] = lds_u32(Bh + n * LDT + kc);
                bh[1] = lds_u32(Bh + n * LDT + kc + 8);
                #pragma unroll
                for (int mi = 0; mi < 2; mi++) {
                    mma16816f16(acc[mi][nj], ah[mi], bh);
                    mma16816f16(acc[mi][nj], al[mi], bh);
                }
            }
        }

        // store stage kt+1 (held in set (kt+1)&1) into the other smem buffer
        if (kt < 7) {
            __half* dst = smh + ((kt + 1) & 1) * STG;
            if (((kt + 1) & 1) == 0) sts_stage(dst, va0, vb0);
            else                     sts_stage(dst, va1, vb1);
        }
        __syncthreads();
    }

    #pragma unroll
    for (int mi = 0; mi < 2; mi++) {
        #pragma unroll
        for (int nj = 0; nj < 8; nj++) {
            int row = m0 + wm * 32 + mi * 16 + g;
            int col = n0 + wn * 64 + nj * 8 + tc * 2;
            float b0 = __ldg(bias + col), b1 = __ldg(bias + col + 1);
            *reinterpret_cast<float2*>(C + (size_t)row * N + col) =
                make_float2(acc[mi][nj][0] + b0, acc[mi][nj][1] + b1);
            *reinterpret_cast<float2*>(C + (size_t)(row + 8) * N + col) =
                make_float2(acc[mi][nj][2] + b0, acc[mi][nj][3] + b1);
        }
    }
}

// =============================================================================
// Fused attention (fp16x2): one CTA per (bt, head-group of 4). 256 threads =
// 8 warps = 2 warps/head. (unchanged from R6 — known good)
// =============================================================================
__global__ __launch_bounds__(256, 2) void attn_kernel(const float* __restrict__ rpb)
{
    extern __shared__ __half smq[];
    __half* qhi = smq;                    // 8704
    __half* qlo = smq + 8704;             // 8704
    __half* khi = smq + 17408;            // 8704
    __half* vhi = smq + 26112;            // 128 x 72 = 9216
    float* srpb = reinterpret_cast<float*>(smq + 35328);

    const int tid = threadIdx.x;
    const int bt = blockIdx.x >> 1;
    const int hg = blockIdx.x & 1;
    const int b = bt >> 1;

    const float* qsrc = g_q + (size_t)b * (64 * 256) + hg * 128;
    const float* kvsrc = g_kv + (size_t)bt * (64 * 512) + hg * 128;

    #pragma unroll
    for (int u = 0; u < 8; u++) {
        int f = tid + u * 256;
        int r = f >> 5;
        int c = (f & 31) << 2;
        float4 v = *reinterpret_cast<const float4*>(qsrc + r * 256 + c);
        split_store_h(v.x, v.y, qhi + r * 136 + c, qlo + r * 136 + c);
        split_store_h(v.z, v.w, qhi + r * 136 + c + 2, qlo + r * 136 + c + 2);
    }
    #pragma unroll
    for (int u = 0; u < 8; u++) {
        int f = tid + u * 256;
        int r = f >> 5;
        int c = (f & 31) << 2;
        float4 v = *reinterpret_cast<const float4*>(kvsrc + r * 512 + c);
        __half* hp = khi + r * 136 + c;
        *reinterpret_cast<__half2*>(hp) = __floats2half2_rn(v.x, v.y);
        *reinterpret_cast<__half2*>(hp + 2) = __floats2half2_rn(v.z, v.w);
    }
    #pragma unroll
    for (int u = 0; u < 8; u++) {
        int f = tid + u * 256;
        int r = f >> 5;
        int c = (f & 31) << 2;
        float4 v = *reinterpret_cast<const float4*>(kvsrc + r * 512 + 256 + c);
        float vals[4] = {v.x, v.y, v.z, v.w};
        #pragma unroll
        for (int j = 0; j < 4; j++)
            vhi[(c + j) * 72 + r] = __float2half(vals[j]);
    }
    for (int i = tid; i < 1800; i += 256) srpb[i] = rpb[i];
    __syncthreads();

    const int warp = tid >> 5, lane = tid & 31;
    const int hl = warp >> 1;
    const int h = hg * 4 + hl;
    const int half = warp & 1;
    const int g = lane >> 2, tc = lane & 3;
    const int r0 = half * 32;

    float S[2][8][4];
    #pragma unroll
    for (int i = 0; i < 2; i++)
        #pragma unroll
        for (int j = 0; j < 8; j++)
            #pragma unroll
            for (int e = 0; e < 4; e++) S[i][j][e] = 0.f;

    #pragma unroll
    for (int kk = 0; kk < 2; kk++) {
        const int kc = hl * 32 + kk * 16 + tc * 2;
        uint ah[2][4], al[2][4];
        #pragma unroll
        for (int mi = 0; mi < 2; mi++) {
            int row = r0 + mi * 16 + g;
            ah[mi][0] = lds_u32(qhi + row * 136 + kc);
            ah[mi][1] = lds_u32(qhi + (row + 8) * 136 + kc);
            ah[mi][2] = lds_u32(qhi + row * 136 + kc + 8);
            ah[mi][3] = lds_u32(qhi + (row + 8) * 136 + kc + 8);
            al[mi][0] = lds_u32(qlo + row * 136 + kc);
            al[mi][1] = lds_u32(qlo + (row + 8) * 136 + kc);
            al[mi][2] = lds_u32(qlo + row * 136 + kc + 8);
            al[mi][3] = lds_u32(qlo + (row + 8) * 136 + kc + 8);
        }
        #pragma unroll
        for (int nj = 0; nj < 8; nj++) {
            int n = nj * 8 + g;
            uint bh[2];
            bh[0] = lds_u32(khi + n * 136 + kc);
            bh[1] = lds_u32(khi + n * 136 + kc + 8);
            #pragma unroll
            for (int mi = 0; mi < 2; mi++) {
                mma16816f16(S[mi][nj], ah[mi], bh);
                mma16816f16(S[mi][nj], al[mi], bh);
            }
        }
    }

    const float scale = 0.17677669529663687f;
    #pragma unroll
    for (int mi = 0; mi < 2; mi++) {
        #pragma unroll
        for (int p = 0; p < 2; p++) {
            int row = r0 + mi * 16 + g + p * 8;
            int pi = row >> 3, pj = row & 7;
            float mx = -1e30f;
            #pragma unroll
            for (int nj = 0; nj < 8; nj++) {
                #pragma unroll
                for (int e = 0; e < 2; e++) {
                    int col = nj * 8 + tc * 2 + e;
                    int qi = col >> 3, qj = col & 7;
                    int rel = (pi - qi + 7) * 15 + (pj - qj + 7);
                    float s = S[mi][nj][p * 2 + e] * scale + srpb[rel * 8 + h];
                    S[mi][nj][p * 2 + e] = s;
                    mx = fmaxf(mx, s);
                }
            }
            mx = fmaxf(mx, __shfl_xor_sync(0xffffffffu, mx, 1));
            mx = fmaxf(mx, __shfl_xor_sync(0xffffffffu, mx, 2));
            float sum = 0.f;
            #pragma unroll
            for (int nj = 0; nj < 8; nj++) {
                #pragma unroll
                for (int e = 0; e < 2; e++) {
                    float pe = __expf(S[mi][nj][p * 2 + e] - mx);
                    S[mi][nj][p * 2 + e] = pe;
                    sum += pe;
                }
            }
            sum += __shfl_xor_sync(0xffffffffu, sum, 1);
            sum += __shfl_xor_sync(0xffffffffu, sum, 2);
            float inv = 1.f / sum;
            #pragma unroll
            for (int nj = 0; nj < 8; nj++) {
                S[mi][nj][p * 2 + 0] *= inv;
                S[mi][nj][p * 2 + 1] *= inv;
            }
        }
    }

    uint phi[2][8][2], plo[2][8][2];
    #pragma unroll
    for (int mi = 0; mi < 2; mi++)
        #pragma unroll
        for (int nj = 0; nj < 8; nj++) {
            packsplit_h(S[mi][nj][0], S[mi][nj][1], phi[mi][nj][0], plo[mi][nj][0]);
            packsplit_h(S[mi][nj][2], S[mi][nj][3], phi[mi][nj][1], plo[mi][nj][1]);
        }

    float O[2][4][4];
    #pragma unroll
    for (int i = 0; i < 2; i++)
        #pragma unroll
        for (int j = 0; j < 4; j++)
            #pragma unroll
            for (int e = 0; e < 4; e++) O[i][j][e] = 0.f;

    #pragma unroll
    for (int t = 0; t < 4; t++) {
        const int kb = t * 16 + tc * 2;
        #pragma unroll
        for (int jn = 0; jn < 4; jn++) {
            int d = hl * 32 + jn * 8 + g;
            uint bh[2];
            bh[0] = lds_u32(vhi + d * 72 + kb);
            bh[1] = lds_u32(vhi + d * 72 + kb + 8);
            #pragma unroll
            for (int mi = 0; mi < 2; mi++) {
                uint pa[4] = {phi[mi][2 * t][0], phi[mi][2 * t][1],
                              phi[mi][2 * t + 1][0], phi[mi][2 * t + 1][1]};
                uint la[4] = {plo[mi][2 * t][0], plo[mi][2 * t][1],
                              plo[mi][2 * t + 1][0], plo[mi][2 * t + 1][1]};
                mma16816f16(O[mi][jn], pa, bh);
                mma16816f16(O[mi][jn], la, bh);
            }
        }
    }

    float* dst = g_att + (size_t)bt * (64 * 256);
    #pragma unroll
    for (int mi = 0; mi < 2; mi++) {
        #pragma unroll
        for (int jn = 0; jn < 4; jn++) {
            int row = r0 + mi * 16 + g;
            int col = h * 32 + jn * 8 + tc * 2;
            *reinterpret_cast<float2*>(dst + row * 256 + col) =
                make_float2(O[mi][jn][0], O[mi][jn][1]);
            *reinterpret_cast<float2*>(dst + (row + 8) * 256 + col) =
                make_float2(O[mi][jn][2], O[mi][jn][3]);
        }
    }
}

// =============================================================================
extern "C" void kernel_launch(void* const* d_in, const int* in_sizes, int n_in,
                              void* d_out, int out_size)
{
    const float* x      = (const float*)d_in[0];
    const float* memory = (const float*)d_in[1];
    const float* q_w    = (const float*)d_in[2];
    const float* q_b    = (const float*)d_in[3];
    const float* kv_w   = (const float*)d_in[4];
    const float* kv_b   = (const float*)d_in[5];
    const float* proj_w = (const float*)d_in[6];
    const float* proj_b = (const float*)d_in[7];
    const float* rpb    = (const float*)d_in[8];
    float* out = (float*)d_out;

    float *qbuf = nullptr, *kvbuf = nullptr, *attbuf = nullptr;
    cudaGetSymbolAddress((void**)&qbuf, g_q);
    cudaGetSymbolAddress((void**)&kvbuf, g_kv);
    cudaGetSymbolAddress((void**)&attbuf, g_att);

    cudaFuncSetAttribute(gemm_kernel,
                         cudaFuncAttributeMaxDynamicSharedMemorySize, 61440);
    cudaFuncSetAttribute(attn_kernel,
                         cudaFuncAttributeMaxDynamicSharedMemorySize, 77856);

    // q projection: (2048*64, 256) @ (256, 256)^T
    gemm_kernel<<<dim3(2, 1024), 256, 61440>>>(x, q_w, q_b, qbuf, 256);
    // kv projection: (4096*64, 256) @ (512, 256)^T
    gemm_kernel<<<dim3(4, 2048), 256, 61440>>>(memory, kv_w, kv_b, kvbuf, 512);
    // fused attention: 2 CTAs (4 heads each) per (b, t)
    attn_kernel<<<8192, 256, 77856>>>(rpb);
    // output projection: (4096*64, 256) @ (256, 256)^T
    gemm_kernel<<<dim3(2, 2048), 256, 61440>>>(attbuf, proj_w, proj_b, out, 256);
}

// round 9
// speedup vs baseline: 1.5327x; 1.0113x over previous
#include <cuda_runtime.h>
#include <cuda_bf16.h>
#include <cuda_fp16.h>

typedef unsigned int uint;

// ---------------- scratch (device globals; no allocs allowed) ----------------
// all intermediates fp16 (hi / compensated-lo planes)
__device__ __half g_qh[2048L * 64 * 256];   // 64 MB  q hi
__device__ __half g_ql[2048L * 64 * 256];   // 64 MB  q lo
__device__ __half g_kh[4096L * 64 * 256];   // 128 MB k hi
__device__ __half g_vh[4096L * 64 * 256];   // 128 MB v hi (seq-major)
__device__ __half g_oh[4096L * 64 * 256];   // 128 MB attention out hi
__device__ __half g_ol[4096L * 64 * 256];   // 128 MB attention out lo

#define DEV_INLINE __device__ __forceinline__

DEV_INLINE void mma16816f16(float* d, const uint* a, const uint* b) {
    asm volatile(
        "mma.sync.aligned.m16n8k16.row.col.f32.f16.f16.f32 "
        "{%0,%1,%2,%3}, {%4,%5,%6,%7}, {%8,%9}, {%0,%1,%2,%3};\n"
        : "+f"(d[0]), "+f"(d[1]), "+f"(d[2]), "+f"(d[3])
        : "r"(a[0]), "r"(a[1]), "r"(a[2]), "r"(a[3]), "r"(b[0]), "r"(b[1]));
}

DEV_INLINE uint lds_u32(const void* p) { return *reinterpret_cast<const uint*>(p); }

DEV_INLINE uint sm_u32(const void* p) {
    uint a;
    asm("{ .reg .u64 t; cvta.to.shared.u64 t, %1; cvt.u32.u64 %0, t; }" : "=r"(a) : "l"(p));
    return a;
}

#define CP16(dst, src) \
    asm volatile("cp.async.cg.shared.global [%0], [%1], 16;" :: "r"(dst), "l"(src))
#define CP_COMMIT() asm volatile("cp.async.commit_group;" ::: "memory")
#define CP_WAIT(n)  asm volatile("cp.async.wait_group %0;" :: "n"(n) : "memory")

DEV_INLINE void ldsm_x4(uint* r, uint a) {
    asm volatile("ldmatrix.sync.aligned.m8n8.x4.shared.b16 {%0,%1,%2,%3}, [%4];"
                 : "=r"(r[0]), "=r"(r[1]), "=r"(r[2]), "=r"(r[3]) : "r"(a));
}
DEV_INLINE void ldsm_x2(uint* r, uint a) {
    asm volatile("ldmatrix.sync.aligned.m8n8.x2.shared.b16 {%0,%1}, [%2];"
                 : "=r"(r[0]), "=r"(r[1]) : "r"(a));
}
DEV_INLINE void ldsm_x2t(uint* r, uint a) {
    asm volatile("ldmatrix.sync.aligned.m8n8.x2.trans.shared.b16 {%0,%1}, [%2];"
                 : "=r"(r[0]), "=r"(r[1]) : "r"(a));
}

DEV_INLINE void split_store_h(float x, float y, __half* hi_p, __half* lo_p) {
    __half2 h = __floats2half2_rn(x, y);
    __half2 l = __floats2half2_rn(x - __half2float(__low2half(h)),
                                  y - __half2float(__high2half(h)));
    *reinterpret_cast<__half2*>(hi_p) = h;
    *reinterpret_cast<__half2*>(lo_p) = l;
}

DEV_INLINE void packsplit_h(float x, float y, uint& hi, uint& lo) {
    __half2 h = __floats2half2_rn(x, y);
    __half2 l = __floats2half2_rn(x - __half2float(__low2half(h)),
                                  y - __half2float(__high2half(h)));
    hi = *reinterpret_cast<uint*>(&h);
    lo = *reinterpret_cast<uint*>(&l);
}

DEV_INLINE uint pack_h(float x, float y) {
    __half2 h = __floats2half2_rn(x, y);
    return *reinterpret_cast<uint*>(&h);
}

// =============================================================================
// GEMM (fp32 in, fp16 out): C = A[M,256] @ B[N,256]^T + bias. fp16x2 compute.
// R8-proven pipelined body. mode 0: q (hi+lo planes, N=256).
// mode 1: kv (cols<256 -> k hi; cols>=256 -> v hi; N=512).
// =============================================================================
__global__ __launch_bounds__(256, 1) void gemm_f16o_kernel(
    const float* __restrict__ A, const float* __restrict__ B,
    const float* __restrict__ bias, __half* __restrict__ C1,
    __half* __restrict__ C2, int N, int mode)
{
    constexpr int K = 256;
    constexpr int LDT = 40;
    constexpr int STG = 15360;
    extern __shared__ __half smh[];

    const int tid = threadIdx.x;
    const int m0 = blockIdx.y * 128;
    const int n0 = blockIdx.x * 128;

    const int lr = tid >> 3;
    const int lc = (tid & 7) << 2;

    float4 va0[4], vb0[4], va1[4], vb1[4];

    auto ldg_stage = [&](int k0, float4 (&va)[4], float4 (&vb)[4]) {
        #pragma unroll
        for (int u = 0; u < 4; u++) {
            int r = lr + u * 32;
            va[u] = *reinterpret_cast<const float4*>(A + (size_t)(m0 + r) * K + k0 + lc);
            vb[u] = *reinterpret_cast<const float4*>(B + (size_t)(n0 + r) * K + k0 + lc);
        }
    };
    auto sts_stage = [&](__half* st, const float4 (&va)[4], const float4 (&vb)[4]) {
        #pragma unroll
        for (int u = 0; u < 4; u++) {
            int r = lr + u * 32;
            __half* hp = st + r * LDT + lc;
            __half* lp = st + 5120 + r * LDT + lc;
            split_store_h(va[u].x, va[u].y, hp, lp);
            split_store_h(va[u].z, va[u].w, hp + 2, lp + 2);
            __half* bp = st + 10240 + r * LDT + lc;
            *reinterpret_cast<__half2*>(bp) = __floats2half2_rn(vb[u].x, vb[u].y);
            *reinterpret_cast<__half2*>(bp + 2) = __floats2half2_rn(vb[u].z, vb[u].w);
        }
    };

    const int warp = tid >> 5, lane = tid & 31;
    const int wm = warp & 3, wn = warp >> 2;
    const int g = lane >> 2, tc = lane & 3;

    float acc[2][8][4];
    #pragma unroll
    for (int i = 0; i < 2; i++)
        #pragma unroll
        for (int j = 0; j < 8; j++)
            #pragma unroll
            for (int e = 0; e < 4; e++) acc[i][j][e] = 0.f;

    ldg_stage(0, va0, vb0);
    sts_stage(smh, va0, vb0);
    ldg_stage(32, va1, vb1);
    __syncthreads();

    #pragma unroll
    for (int kt = 0; kt < 8; kt++) {
        if (kt < 6) {
            if ((kt & 1) == 0) ldg_stage((kt + 2) * 32, va0, vb0);
            else               ldg_stage((kt + 2) * 32, va1, vb1);
        }
        const __half* st = smh + (kt & 1) * STG;
        const __half* Ah = st;
        const __half* Al = st + 5120;
        const __half* Bh = st + 10240;

        #pragma unroll
        for (int kk = 0; kk < 2; kk++) {
            const int kc = kk * 16 + tc * 2;
            uint ah[2][4], al[2][4];
            #pragma unroll
            for (int mi = 0; mi < 2; mi++) {
                int row = wm * 32 + mi * 16 + g;
                ah[mi][0] = lds_u32(Ah + row * LDT + kc);
                ah[mi][1] = lds_u32(Ah + (row + 8) * LDT + kc);
                ah[mi][2] = lds_u32(Ah + row * LDT + kc + 8);
                ah[mi][3] = lds_u32(Ah + (row + 8) * LDT + kc + 8);
                al[mi][0] = lds_u32(Al + row * LDT + kc);
                al[mi][1] = lds_u32(Al + (row + 8) * LDT + kc);
                al[mi][2] = lds_u32(Al + row * LDT + kc + 8);
                al[mi][3] = lds_u32(Al + (row + 8) * LDT + kc + 8);
            }
            #pragma unroll
            for (int nj = 0; nj < 8; nj++) {
                int n = wn * 64 + nj * 8 + g;
                uint bh[2];
                bh[0] = lds_u32(Bh + n * LDT + kc);
                bh[1] = lds_u32(Bh + n * LDT + kc + 8);
                #pragma unroll
                for (int mi = 0; mi < 2; mi++) {
                    mma16816f16(acc[mi][nj], ah[mi], bh);
                    mma16816f16(acc[mi][nj], al[mi], bh);
                }
            }
        }
        if (kt < 7) {
            __half* dst = smh + ((kt + 1) & 1) * STG;
            if (((kt + 1) & 1) == 0) sts_stage(dst, va0, vb0);
            else                     sts_stage(dst, va1, vb1);
        }
        __syncthreads();
    }

    #pragma unroll
    for (int mi = 0; mi < 2; mi++) {
        #pragma unroll
        for (int nj = 0; nj < 8; nj++) {
            int row = m0 + wm * 32 + mi * 16 + g;
            int col = n0 + wn * 64 + nj * 8 + tc * 2;
            float b0 = __ldg(bias + col), b1 = __ldg(bias + col + 1);
            float x0 = acc[mi][nj][0] + b0, y0 = acc[mi][nj][1] + b1;
            float x1 = acc[mi][nj][2] + b0, y1 = acc[mi][nj][3] + b1;
            if (mode == 0) {                      // q: hi + lo planes
                size_t o0 = (size_t)row * 256 + col;
                size_t o1 = (size_t)(row + 8) * 256 + col;
                uint h, l;
                packsplit_h(x0, y0, h, l);
                *reinterpret_cast<uint*>(C1 + o0) = h;
                *reinterpret_cast<uint*>(C2 + o0) = l;
                packsplit_h(x1, y1, h, l);
                *reinterpret_cast<uint*>(C1 + o1) = h;
                *reinterpret_cast<uint*>(C2 + o1) = l;
            } else {                              // kv: k hi | v hi
                __half* dst = (col < 256) ? C1 : C2;
                int cc = (col < 256) ? col : col - 256;
                *reinterpret_cast<uint*>(dst + (size_t)row * 256 + cc) = pack_h(x0, y0);
                *reinterpret_cast<uint*>(dst + (size_t)(row + 8) * 256 + cc) = pack_h(x1, y1);
            }
        }
    }
}

// =============================================================================
// Fused attention (all-fp16 inputs via cp.async + ldmatrix).
// One CTA per (bt, head-group of 4). 256 threads = 8 warps = 2 warps/head.
// smem bytes: qhi 0 | qlo 17408 | kh 34816 | vh 52224 ([seq][d]) | rpb 69632.
// total 76832 -> 2 CTAs/SM.
// =============================================================================
__global__ __launch_bounds__(256, 2) void attn_kernel(const float* __restrict__ rpb)
{
    extern __shared__ char smc[];
    const uint sb = sm_u32(smc);
    const uint QH = sb, QL = sb + 17408, KH = sb + 34816, VH = sb + 52224;
    float* srpb = reinterpret_cast<float*>(smc + 69632);

    const int tid = threadIdx.x;
    const int bt = blockIdx.x >> 1;
    const int hg = blockIdx.x & 1;
    const int b = bt >> 1;

    const __half* qh_src = g_qh + (size_t)b * (64 * 256) + hg * 128;
    const __half* ql_src = g_ql + (size_t)b * (64 * 256) + hg * 128;
    const __half* kh_src = g_kh + (size_t)bt * (64 * 256) + hg * 128;
    const __half* vh_src = g_vh + (size_t)bt * (64 * 256) + hg * 128;

    // ---- async stage: 4 x (64 rows x 128 halves), 16B chunks ----
    #pragma unroll
    for (int u = 0; u < 4; u++) {
        int f = tid + u * 256;           // chunk id 0..1023
        int r = f >> 4;                  // row
        int cc = (f & 15) << 3;          // col (halves)
        uint doff = (uint)(r * 136 + cc) * 2;
        size_t soff = (size_t)r * 256 + cc;
        CP16(QH + doff, qh_src + soff);
        CP16(QL + doff, ql_src + soff);
        CP16(KH + doff, kh_src + soff);
        CP16(VH + doff, vh_src + soff);
    }
    for (int i = tid; i < 450; i += 256)
        CP16(sb + 69632 + i * 16, rpb + i * 4);
    CP_COMMIT();
    CP_WAIT(0);
    __syncthreads();

    const int warp = tid >> 5, lane = tid & 31;
    const int hl = warp >> 1;
    const int h = hg * 4 + hl;
    const int half = warp & 1;
    const int g = lane >> 2, tc = lane & 3;
    const int r0 = half * 32;

    // ---- S = (qh + ql) @ kh^T (32 x 64) ----
    float S[2][8][4];
    #pragma unroll
    for (int i = 0; i < 2; i++)
        #pragma unroll
        for (int j = 0; j < 8; j++)
            #pragma unroll
            for (int e = 0; e < 4; e++) S[i][j][e] = 0.f;

    #pragma unroll
    for (int kk = 0; kk < 2; kk++) {
        const int kc0 = hl * 32 + kk * 16;
        uint ah[2][4], al[2][4];
        #pragma unroll
        for (int mi = 0; mi < 2; mi++) {
            int arow = r0 + mi * 16 + (lane & 15);
            int acol = kc0 + (lane >> 4) * 8;
            uint aoff = (uint)(arow * 136 + acol) * 2;
            ldsm_x4(ah[mi], QH + aoff);
            ldsm_x4(al[mi], QL + aoff);
        }
        #pragma unroll
        for (int nj = 0; nj < 8; nj++) {
            int brow = nj * 8 + (lane & 7);
            int bcol = kc0 + ((lane >> 3) & 1) * 8;
            uint bh[2];
            ldsm_x2(bh, KH + (uint)(brow * 136 + bcol) * 2);
            #pragma unroll
            for (int mi = 0; mi < 2; mi++) {
                mma16816f16(S[mi][nj], ah[mi], bh);
                mma16816f16(S[mi][nj], al[mi], bh);
            }
        }
    }

    // ---- scale + relative-position bias + softmax (fp32) ----
    const float scale = 0.17677669529663687f;
    #pragma unroll
    for (int mi = 0; mi < 2; mi++) {
        #pragma unroll
        for (int p = 0; p < 2; p++) {
            int row = r0 + mi * 16 + g + p * 8;
            int pi = row >> 3, pj = row & 7;
            float mx = -1e30f;
            #pragma unroll
            for (int nj = 0; nj < 8; nj++) {
                #pragma unroll
                for (int e = 0; e < 2; e++) {
                    int col = nj * 8 + tc * 2 + e;
                    int qi = col >> 3, qj = col & 7;
                    int rel = (pi - qi + 7) * 15 + (pj - qj + 7);
                    float s = S[mi][nj][p * 2 + e] * scale + srpb[rel * 8 + h];
                    S[mi][nj][p * 2 + e] = s;
                    mx = fmaxf(mx, s);
                }
            }
            mx = fmaxf(mx, __shfl_xor_sync(0xffffffffu, mx, 1));
            mx = fmaxf(mx, __shfl_xor_sync(0xffffffffu, mx, 2));
            float sum = 0.f;
            #pragma unroll
            for (int nj = 0; nj < 8; nj++) {
                #pragma unroll
                for (int e = 0; e < 2; e++) {
                    float pe = __expf(S[mi][nj][p * 2 + e] - mx);
                    S[mi][nj][p * 2 + e] = pe;
                    sum += pe;
                }
            }
            sum += __shfl_xor_sync(0xffffffffu, sum, 1);
            sum += __shfl_xor_sync(0xffffffffu, sum, 2);
            float inv = 1.f / sum;
            #pragma unroll
            for (int nj = 0; nj < 8; nj++) {
                S[mi][nj][p * 2 + 0] *= inv;
                S[mi][nj][p * 2 + 1] *= inv;
            }
        }
    }

    // ---- pack P to fp16 hi/lo ----
    uint phi[2][8][2], plo[2][8][2];
    #pragma unroll
    for (int mi = 0; mi < 2; mi++)
        #pragma unroll
        for (int nj = 0; nj < 8; nj++) {
            packsplit_h(S[mi][nj][0], S[mi][nj][1], phi[mi][nj][0], plo[mi][nj][0]);
            packsplit_h(S[mi][nj][2], S[mi][nj][3], phi[mi][nj][1], plo[mi][nj][1]);
        }

    // ---- O = (Ph + Pl) @ Vh  (V frags via ldmatrix.trans from [seq][d]) ----
    float O[2][4][4];
    #pragma unroll
    for (int i = 0; i < 2; i++)
        #pragma unroll
        for (int j = 0; j < 4; j++)
            #pragma unroll
            for (int e = 0; e < 4; e++) O[i][j][e] = 0.f;

    #pragma unroll
    for (int t = 0; t < 4; t++) {
        #pragma unroll
        for (int jn = 0; jn < 4; jn++) {
            int vrow = t * 16 + (lane & 7) + ((lane >> 3) & 1) * 8;
            int vcol = hl * 32 + jn * 8;
            uint bh[2];
            ldsm_x2t(bh, VH + (uint)(vrow * 136 + vcol) * 2);
            #pragma unroll
            for (int mi = 0; mi < 2; mi++) {
                uint pa[4] = {phi[mi][2 * t][0], phi[mi][2 * t][1],
                              phi[mi][2 * t + 1][0], phi[mi][2 * t + 1][1]};
                uint la[4] = {plo[mi][2 * t][0], plo[mi][2 * t][1],
                              plo[mi][2 * t + 1][0], plo[mi][2 * t + 1][1]};
                mma16816f16(O[mi][jn], pa, bh);
                mma16816f16(O[mi][jn], la, bh);
            }
        }
    }

    // ---- write O as fp16 hi/lo planes ----
    __half* doh = g_oh + (size_t)bt * (64 * 256);
    __half* dol = g_ol + (size_t)bt * (64 * 256);
    #pragma unroll
    for (int mi = 0; mi < 2; mi++) {
        #pragma unroll
        for (int jn = 0; jn < 4; jn++) {
            int row = r0 + mi * 16 + g;
            int col = h * 32 + jn * 8 + tc * 2;
            uint hh, ll;
            packsplit_h(O[mi][jn][0], O[mi][jn][1], hh, ll);
            *reinterpret_cast<uint*>(doh + row * 256 + col) = hh;
            *reinterpret_cast<uint*>(dol + row * 256 + col) = ll;
            packsplit_h(O[mi][jn][2], O[mi][jn][3], hh, ll);
            *reinterpret_cast<uint*>(doh + (row + 8) * 256 + col) = hh;
            *reinterpret_cast<uint*>(dol + (row + 8) * 256 + col) = ll;
        }
    }
}

// =============================================================================
// proj GEMM: out = (Oh + Ol)[M,256] @ proj_w[256,256]^T + bias. fp32 out.
// A planes fp16 in global -> cp.async direct (no convert). B fp32 -> reg pipe.
// 256 thr, BM=128, BN=128, BK=32, 2 stages.
// =============================================================================
__global__ __launch_bounds__(256, 1) void proj_kernel(
    const __half* __restrict__ Ahg, const __half* __restrict__ Alg,
    const float* __restrict__ W, const float* __restrict__ bias,
    float* __restrict__ C)
{
    constexpr int K = 256;
    constexpr int LDT = 40;
    constexpr int STG_B = 30720;       // stage bytes (Ahi 10240 | Alo 10240 | Bh 10240)
    extern __shared__ __half smh[];
    const uint sb = sm_u32(smh);

    const int tid = threadIdx.x;
    const int m0 = blockIdx.y * 128;
    const int n0 = blockIdx.x * 128;

    float4 vb0[2][2], vb1[2][2];

    auto cp_stage = [&](int kt, int s) {
        const int k0 = kt * 32;
        const uint base = sb + s * STG_B;
        #pragma unroll
        for (int u = 0; u < 2; u++) {
            int f = tid + u * 256;       // 0..511
            int r = f >> 2;              // row
            int cc = (f & 3) << 3;       // col halves
            uint doff = (uint)(r * 80 + cc * 2);
            size_t soff = (size_t)(m0 + r) * K + k0 + cc;
            CP16(base + doff, Ahg + soff);
            CP16(base + 10240 + doff, Alg + soff);
        }
        CP_COMMIT();
    };
    auto ldg_b = [&](int kt, float4 (&vb)[2][2]) {
        const int k0 = kt * 32;
        #pragma unroll
        for (int u = 0; u < 2; u++) {
            int f = tid + u * 256;
            int r = f >> 2;
            int cu = (f & 3) << 3;
            const float* p = W + (size_t)(n0 + r) * K + k0 + cu;
            vb[u][0] = *reinterpret_cast<const float4*>(p);
            vb[u][1] = *reinterpret_cast<const float4*>(p + 4);
        }
    };
    auto sts_b = [&](int s, const float4 (&vb)[2][2]) {
        __half* st = smh + s * (STG_B / 2) + 10240;   // Bh region (halves)
        #pragma unroll
        for (int u = 0; u < 2; u++) {
            int f = tid + u * 256;
            int r = f >> 2;
            int cu = (f & 3) << 3;
            __half* bp = st + r * LDT + cu;
            *reinterpret_cast<__half2*>(bp) = __floats2half2_rn(vb[u][0].x, vb[u][0].y);
            *reinterpret_cast<__half2*>(bp + 2) = __floats2half2_rn(vb[u][0].z, vb[u][0].w);
            *reinterpret_cast<__half2*>(bp + 4) = __floats2half2_rn(vb[u][1].x, vb[u][1].y);
            *reinterpret_cast<__half2*>(bp + 6) = __floats2half2_rn(vb[u][1].z, vb[u][1].w);
        }
    };

    const int warp = tid >> 5, lane = tid & 31;
    const int wm = warp & 3, wn = warp >> 2;
    const int g = lane >> 2, tc = lane & 3;

    float acc[2][8][4];
    #pragma unroll
    for (int i = 0; i < 2; i++)
        #pragma unroll
        for (int j = 0; j < 8; j++)
            #pragma unroll
            for (int e = 0; e < 4; e++) acc[i][j][e] = 0.f;

    // prologue
    cp_stage(0, 0);
    cp_stage(1, 1);
    ldg_b(0, vb0);
    sts_b(0, vb0);
    ldg_b(1, vb1);
    CP_WAIT(0);
    __syncthreads();

    #pragma unroll
    for (int kt = 0; kt < 8; kt++) {
        const __half* st = smh + (kt & 1) * (STG_B / 2);
        const __half* Ah = st;
        const __half* Al = st + 5120;
        const __half* Bh = st + 10240;

        #pragma unroll
        for (int kk = 0; kk < 2; kk++) {
            const int kc = kk * 16 + tc * 2;
            uint ah[2][4], al[2][4];
            #pragma unroll
            for (int mi = 0; mi < 2; mi++) {
                int row = wm * 32 + mi * 16 + g;
                ah[mi][0] = lds_u32(Ah + row * LDT + kc);
                ah[mi][1] = lds_u32(Ah + (row + 8) * LDT + kc);
                ah[mi][2] = lds_u32(Ah + row * LDT + kc + 8);
                ah[mi][3] = lds_u32(Ah + (row + 8) * LDT + kc + 8);
                al[mi][0] = lds_u32(Al + row * LDT + kc);
                al[mi][1] = lds_u32(Al + (row + 8) * LDT + kc);
                al[mi][2] = lds_u32(Al + row * LDT + kc + 8);
                al[mi][3] = lds_u32(Al + (row + 8) * LDT + kc + 8);
            }
            #pragma unroll
            for (int nj = 0; nj < 8; nj++) {
                int n = wn * 64 + nj * 8 + g;
                uint bh[2];
                bh[0] = lds_u32(Bh + n * LDT + kc);
                bh[1] = lds_u32(Bh + n * LDT + kc + 8);
                #pragma unroll
                for (int mi = 0; mi < 2; mi++) {
                    mma16816f16(acc[mi][nj], ah[mi], bh);
                    mma16816f16(acc[mi][nj], al[mi], bh);
                }
            }
        }

        if (kt < 7) {
            if (((kt + 1) & 1) == 0) sts_b((kt + 1) & 1, vb0);
            else                     sts_b((kt + 1) & 1, vb1);
            CP_WAIT(0);
            __syncthreads();
            if (kt < 6) {
                cp_stage(kt + 2, kt & 1);
                if ((kt & 1) == 0) ldg_b(kt + 2, vb0);
                else               ldg_b(kt + 2, vb1);
            }
        }
    }

    #pragma unroll
    for (int mi = 0; mi < 2; mi++) {
        #pragma unroll
        for (int nj = 0; nj < 8; nj++) {
            int row = m0 + wm * 32 + mi * 16 + g;
            int col = n0 + wn * 64 + nj * 8 + tc * 2;
            float b0 = __ldg(bias + col), b1 = __ldg(bias + col + 1);
            *reinterpret_cast<float2*>(C + (size_t)row * 256 + col) =
                make_float2(acc[mi][nj][0] + b0, acc[mi][nj][1] + b1);
            *reinterpret_cast<float2*>(C + (size_t)(row + 8) * 256 + col) =
                make_float2(acc[mi][nj][2] + b0, acc[mi][nj][3] + b1);
        }
    }
}

// =============================================================================
extern "C" void kernel_launch(void* const* d_in, const int* in_sizes, int n_in,
                              void* d_out, int out_size)
{
    const float* x      = (const float*)d_in[0];
    const float* memory = (const float*)d_in[1];
    const float* q_w    = (const float*)d_in[2];
    const float* q_b    = (const float*)d_in[3];
    const float* kv_w   = (const float*)d_in[4];
    const float* kv_b   = (const float*)d_in[5];
    const float* proj_w = (const float*)d_in[6];
    const float* proj_b = (const float*)d_in[7];
    const float* rpb    = (const float*)d_in[8];
    float* out = (float*)d_out;

    __half *qh, *ql, *kh, *vh, *oh, *ol;
    cudaGetSymbolAddress((void**)&qh, g_qh);
    cudaGetSymbolAddress((void**)&ql, g_ql);
    cudaGetSymbolAddress((void**)&kh, g_kh);
    cudaGetSymbolAddress((void**)&vh, g_vh);
    cudaGetSymbolAddress((void**)&oh, g_oh);
    cudaGetSymbolAddress((void**)&ol, g_ol);

    cudaFuncSetAttribute(gemm_f16o_kernel,
                         cudaFuncAttributeMaxDynamicSharedMemorySize, 61440);
    cudaFuncSetAttribute(attn_kernel,
                         cudaFuncAttributeMaxDynamicSharedMemorySize, 76832);
    cudaFuncSetAttribute(proj_kernel,
                         cudaFuncAttributeMaxDynamicSharedMemorySize, 61440);

    // q projection: (2048*64, 256) -> fp16 hi/lo
    gemm_f16o_kernel<<<dim3(2, 1024), 256, 61440>>>(x, q_w, q_b, qh, ql, 256, 0);
    // kv projection: (4096*64, 512) -> k hi, v hi
    gemm_f16o_kernel<<<dim3(4, 2048), 256, 61440>>>(memory, kv_w, kv_b, kh, vh, 512, 1);
    // fused attention: 2 CTAs (4 heads each) per (b, t)
    attn_kernel<<<8192, 256, 76832>>>(rpb);
    // output projection: fp16 A planes -> fp32 out
    proj_kernel<<<dim3(2, 2048), 256, 61440>>>(oh, ol, proj_w, proj_b, out);
}

// round 10
// speedup vs baseline: 2.3462x; 1.5308x over previous
#include <cuda_runtime.h>
#include <cuda_fp16.h>

typedef unsigned int uint;

// ---------------- scratch (device globals; no allocs allowed) ----------------
__device__ __half g_qh[2048L * 64 * 256];   // 64 MB  q hi
__device__ __half g_ql[2048L * 64 * 256];   // 64 MB  q lo
__device__ __half g_kh[4096L * 64 * 256];   // 128 MB k hi
__device__ __half g_vh[4096L * 64 * 256];   // 128 MB v hi (seq-major)
__device__ __half g_oh[4096L * 64 * 256];   // 128 MB attention out (hi only)
__device__ __half g_wq[256 * 256];          // fp16 weights (pre-converted)
__device__ __half g_wkv[512 * 256];
__device__ __half g_wp[256 * 256];

#define DEV_INLINE __device__ __forceinline__

DEV_INLINE void mma16816f16(float* d, const uint* a, const uint* b) {
    asm volatile(
        "mma.sync.aligned.m16n8k16.row.col.f32.f16.f16.f32 "
        "{%0,%1,%2,%3}, {%4,%5,%6,%7}, {%8,%9}, {%0,%1,%2,%3};\n"
        : "+f"(d[0]), "+f"(d[1]), "+f"(d[2]), "+f"(d[3])
        : "r"(a[0]), "r"(a[1]), "r"(a[2]), "r"(a[3]), "r"(b[0]), "r"(b[1]));
}

DEV_INLINE uint lds_u32(const void* p) { return *reinterpret_cast<const uint*>(p); }

DEV_INLINE uint sm_u32(const void* p) {
    uint a;
    asm("{ .reg .u64 t; cvta.to.shared.u64 t, %1; cvt.u32.u64 %0, t; }" : "=r"(a) : "l"(p));
    return a;
}

#define CP16(dst, src) \
    asm volatile("cp.async.cg.shared.global [%0], [%1], 16;" :: "r"(dst), "l"(src))
#define CP_COMMIT() asm volatile("cp.async.commit_group;" ::: "memory")
#define CP_WAIT(n)  asm volatile("cp.async.wait_group %0;" :: "n"(n) : "memory")

DEV_INLINE void ldsm_x4(uint* r, uint a) {
    asm volatile("ldmatrix.sync.aligned.m8n8.x4.shared.b16 {%0,%1,%2,%3}, [%4];"
                 : "=r"(r[0]), "=r"(r[1]), "=r"(r[2]), "=r"(r[3]) : "r"(a));
}
DEV_INLINE void ldsm_x2(uint* r, uint a) {
    asm volatile("ldmatrix.sync.aligned.m8n8.x2.shared.b16 {%0,%1}, [%2];"
                 : "=r"(r[0]), "=r"(r[1]) : "r"(a));
}
DEV_INLINE void ldsm_x2t(uint* r, uint a) {
    asm volatile("ldmatrix.sync.aligned.m8n8.x2.trans.shared.b16 {%0,%1}, [%2];"
                 : "=r"(r[0]), "=r"(r[1]) : "r"(a));
}

DEV_INLINE void split_store_h(float x, float y, __half* hi_p, __half* lo_p) {
    __half2 h = __floats2half2_rn(x, y);
    __half2 l = __floats2half2_rn(x - __half2float(__low2half(h)),
                                  y - __half2float(__high2half(h)));
    *reinterpret_cast<__half2*>(hi_p) = h;
    *reinterpret_cast<__half2*>(lo_p) = l;
}

DEV_INLINE void packsplit_h(float x, float y, uint& hi, uint& lo) {
    __half2 h = __floats2half2_rn(x, y);
    __half2 l = __floats2half2_rn(x - __half2float(__low2half(h)),
                                  y - __half2float(__high2half(h)));
    hi = *reinterpret_cast<uint*>(&h);
    lo = *reinterpret_cast<uint*>(&l);
}

DEV_INLINE uint pack_h(float x, float y) {
    __half2 h = __floats2half2_rn(x, y);
    return *reinterpret_cast<uint*>(&h);
}

// =============================================================================
// weight pre-convert: fp32 -> fp16 (one shot, bandwidth-trivial)
// =============================================================================
__global__ __launch_bounds__(256) void wconv_kernel(
    const float* __restrict__ qw, const float* __restrict__ kvw,
    const float* __restrict__ pw)
{
    int i = (blockIdx.x * 256 + threadIdx.x) * 4;
    if (i < 65536) {
        float4 v = *reinterpret_cast<const float4*>(qw + i);
        uint2 o; o.x = pack_h(v.x, v.y); o.y = pack_h(v.z, v.w);
        *reinterpret_cast<uint2*>(g_wq + i) = o;
    }
    if (i < 131072) {
        float4 v = *reinterpret_cast<const float4*>(kvw + i);
        uint2 o; o.x = pack_h(v.x, v.y); o.y = pack_h(v.z, v.w);
        *reinterpret_cast<uint2*>(g_wkv + i) = o;
    }
    if (i < 65536) {
        float4 v = *reinterpret_cast<const float4*>(pw + i);
        uint2 o; o.x = pack_h(v.x, v.y); o.y = pack_h(v.z, v.w);
        *reinterpret_cast<uint2*>(g_wp + i) = o;
    }
}

// =============================================================================
// q GEMM: qh/ql = split( x[M,256] @ wq^T + b ). fp16x2 compute (A hi+lo).
// A fp32 reg-pipelined; B fp16 cp.async. 256 thr, BM128/BN128/BK32, 2 stages.
// stage halves: Ah 5120 | Al 5120 | Bh 5120 -> 30720 B; x2 = 61440.
// =============================================================================
__global__ __launch_bounds__(256, 1) void gemm_q_kernel(
    const float* __restrict__ A, const __half* __restrict__ Bw,
    const float* __restrict__ bias, __half* __restrict__ C1,
    __half* __restrict__ C2)
{
    constexpr int K = 256, LDT = 40, STG_H = 15360;
    extern __shared__ __half smh[];
    const uint sb = sm_u32(smh);
    const int tid = threadIdx.x;
    const int m0 = blockIdx.y * 128, n0 = blockIdx.x * 128;
    const int lr = tid >> 3, lc = (tid & 7) << 2;

    float4 va0[4], va1[4];
    auto ldg_a = [&](int kt, float4 (&va)[4]) {
        int k0 = kt * 32;
        #pragma unroll
        for (int u = 0; u < 4; u++) {
            int r = lr + u * 32;
            va[u] = *reinterpret_cast<const float4*>(A + (size_t)(m0 + r) * K + k0 + lc);
        }
    };
    auto sts_a = [&](int s, const float4 (&va)[4]) {
        __half* st = smh + s * STG_H;
        #pragma unroll
        for (int u = 0; u < 4; u++) {
            int r = lr + u * 32;
            __half* hp = st + r * LDT + lc;
            __half* lp = st + 5120 + r * LDT + lc;
            split_store_h(va[u].x, va[u].y, hp, lp);
            split_store_h(va[u].z, va[u].w, hp + 2, lp + 2);
        }
    };
    auto cp_b = [&](int kt, int s) {
        int k0 = kt * 32;
        #pragma unroll
        for (int u = 0; u < 2; u++) {
            int f = tid + u * 256;
            int r = f >> 2, c = (f & 3) << 3;
            uint dst = sb + (uint)(s * STG_H + 10240 + r * LDT + c) * 2;
            CP16(dst, Bw + (size_t)(n0 + r) * K + k0 + c);
        }
        CP_COMMIT();
    };

    const int warp = tid >> 5, lane = tid & 31;
    const int wm = warp & 3, wn = warp >> 2;
    const int g = lane >> 2, tc = lane & 3;

    float acc[2][8][4];
    #pragma unroll
    for (int i = 0; i < 2; i++)
        #pragma unroll
        for (int j = 0; j < 8; j++)
            #pragma unroll
            for (int e = 0; e < 4; e++) acc[i][j][e] = 0.f;

    cp_b(0, 0);
    cp_b(1, 1);
    ldg_a(0, va0);
    sts_a(0, va0);
    ldg_a(1, va1);
    CP_WAIT(0);
    __syncthreads();

    #pragma unroll
    for (int kt = 0; kt < 8; kt++) {
        if (kt < 6) {
            if ((kt & 1) == 0) ldg_a(kt + 2, va0);
            else               ldg_a(kt + 2, va1);
        }
        const __half* st = smh + (kt & 1) * STG_H;
        const __half* Ah = st;
        const __half* Al = st + 5120;
        const __half* Bh = st + 10240;

        #pragma unroll
        for (int kk = 0; kk < 2; kk++) {
            const int kc = kk * 16 + tc * 2;
            uint ah[2][4], al[2][4];
            #pragma unroll
            for (int mi = 0; mi < 2; mi++) {
                int row = wm * 32 + mi * 16 + g;
                ah[mi][0] = lds_u32(Ah + row * LDT + kc);
                ah[mi][1] = lds_u32(Ah + (row + 8) * LDT + kc);
                ah[mi][2] = lds_u32(Ah + row * LDT + kc + 8);
                ah[mi][3] = lds_u32(Ah + (row + 8) * LDT + kc + 8);
                al[mi][0] = lds_u32(Al + row * LDT + kc);
                al[mi][1] = lds_u32(Al + (row + 8) * LDT + kc);
                al[mi][2] = lds_u32(Al + row * LDT + kc + 8);
                al[mi][3] = lds_u32(Al + (row + 8) * LDT + kc + 8);
            }
            #pragma unroll
            for (int nj = 0; nj < 8; nj++) {
                int n = wn * 64 + nj * 8 + g;
                uint bh[2];
                bh[0] = lds_u32(Bh + n * LDT + kc);
                bh[1] = lds_u32(Bh + n * LDT + kc + 8);
                #pragma unroll
                for (int mi = 0; mi < 2; mi++) {
                    mma16816f16(acc[mi][nj], ah[mi], bh);
                    mma16816f16(acc[mi][nj], al[mi], bh);
                }
            }
        }
        __syncthreads();
        if (kt < 6) cp_b(kt + 2, kt & 1);
        if (kt < 7) {
            if (((kt + 1) & 1) == 0) sts_a((kt + 1) & 1, va0);
            else                     sts_a((kt + 1) & 1, va1);
            if (kt < 6) { CP_WAIT(1); } else { CP_WAIT(0); }
            __syncthreads();
        }
    }

    #pragma unroll
    for (int mi = 0; mi < 2; mi++) {
        #pragma unroll
        for (int nj = 0; nj < 8; nj++) {
            int row = m0 + wm * 32 + mi * 16 + g;
            int col = n0 + wn * 64 + nj * 8 + tc * 2;
            float b0 = __ldg(bias + col), b1 = __ldg(bias + col + 1);
            size_t o0 = (size_t)row * 256 + col;
            size_t o1 = (size_t)(row + 8) * 256 + col;
            uint h, l;
            packsplit_h(acc[mi][nj][0] + b0, acc[mi][nj][1] + b1, h, l);
            *reinterpret_cast<uint*>(C1 + o0) = h;
            *reinterpret_cast<uint*>(C2 + o0) = l;
            packsplit_h(acc[mi][nj][2] + b0, acc[mi][nj][3] + b1, h, l);
            *reinterpret_cast<uint*>(C1 + o1) = h;
            *reinterpret_cast<uint*>(C2 + o1) = l;
        }
    }
}

// =============================================================================
// kv GEMM (hi-only A): k/v = round_fp16( mem[M,256] @ wkv^T + b ).
// A fp32 reg-pipelined hi-only; B fp16 cp.async. occ 2.
// stage halves: Ah 5120 | Bh 5120 -> 20480 B; x2 = 40960.
// =============================================================================
__global__ __launch_bounds__(256, 2) void gemm_kv_kernel(
    const float* __restrict__ A, const __half* __restrict__ Bw,
    const float* __restrict__ bias, __half* __restrict__ C1,
    __half* __restrict__ C2)
{
    constexpr int K = 256, LDT = 40, STG_H = 10240;
    extern __shared__ __half smh[];
    const uint sb = sm_u32(smh);
    const int tid = threadIdx.x;
    const int m0 = blockIdx.y * 128, n0 = blockIdx.x * 128;
    const int lr = tid >> 3, lc = (tid & 7) << 2;

    float4 va0[4], va1[4];
    auto ldg_a = [&](int kt, float4 (&va)[4]) {
        int k0 = kt * 32;
        #pragma unroll
        for (int u = 0; u < 4; u++) {
            int r = lr + u * 32;
            va[u] = *reinterpret_cast<const float4*>(A + (size_t)(m0 + r) * K + k0 + lc);
        }
    };
    auto sts_a = [&](int s, const float4 (&va)[4]) {
        __half* st = smh + s * STG_H;
        #pragma unroll
        for (int u = 0; u < 4; u++) {
            int r = lr + u * 32;
            __half* hp = st + r * LDT + lc;
            *reinterpret_cast<__half2*>(hp) = __floats2half2_rn(va[u].x, va[u].y);
            *reinterpret_cast<__half2*>(hp + 2) = __floats2half2_rn(va[u].z, va[u].w);
        }
    };
    auto cp_b = [&](int kt, int s) {
        int k0 = kt * 32;
        #pragma unroll
        for (int u = 0; u < 2; u++) {
            int f = tid + u * 256;
            int r = f >> 2, c = (f & 3) << 3;
            uint dst = sb + (uint)(s * STG_H + 5120 + r * LDT + c) * 2;
            CP16(dst, Bw + (size_t)(n0 + r) * K + k0 + c);
        }
        CP_COMMIT();
    };

    const int warp = tid >> 5, lane = tid & 31;
    const int wm = warp & 3, wn = warp >> 2;
    const int g = lane >> 2, tc = lane & 3;

    float acc[2][8][4];
    #pragma unroll
    for (int i = 0; i < 2; i++)
        #pragma unroll
        for (int j = 0; j < 8; j++)
            #pragma unroll
            for (int e = 0; e < 4; e++) acc[i][j][e] = 0.f;

    cp_b(0, 0);
    cp_b(1, 1);
    ldg_a(0, va0);
    sts_a(0, va0);
    ldg_a(1, va1);
    CP_WAIT(0);
    __syncthreads();

    #pragma unroll
    for (int kt = 0; kt < 8; kt++) {
        if (kt < 6) {
            if ((kt & 1) == 0) ldg_a(kt + 2, va0);
            else               ldg_a(kt + 2, va1);
        }
        const __half* st = smh + (kt & 1) * STG_H;
        const __half* Ah = st;
        const __half* Bh = st + 5120;

        #pragma unroll
        for (int kk = 0; kk < 2; kk++) {
            const int kc = kk * 16 + tc * 2;
            uint ah[2][4];
            #pragma unroll
            for (int mi = 0; mi < 2; mi++) {
                int row = wm * 32 + mi * 16 + g;
                ah[mi][0] = lds_u32(Ah + row * LDT + kc);
                ah[mi][1] = lds_u32(Ah + (row + 8) * LDT + kc);
                ah[mi][2] = lds_u32(Ah + row * LDT + kc + 8);
                ah[mi][3] = lds_u32(Ah + (row + 8) * LDT + kc + 8);
            }
            #pragma unroll
            for (int nj = 0; nj < 8; nj++) {
                int n = wn * 64 + nj * 8 + g;
                uint bh[2];
                bh[0] = lds_u32(Bh + n * LDT + kc);
                bh[1] = lds_u32(Bh + n * LDT + kc + 8);
                #pragma unroll
                for (int mi = 0; mi < 2; mi++)
                    mma16816f16(acc[mi][nj], ah[mi], bh);
            }
        }
        __syncthreads();
        if (kt < 6) cp_b(kt + 2, kt & 1);
        if (kt < 7) {
            if (((kt + 1) & 1) == 0) sts_a((kt + 1) & 1, va0);
            else                     sts_a((kt + 1) & 1, va1);
            if (kt < 6) { CP_WAIT(1); } else { CP_WAIT(0); }
            __syncthreads();
        }
    }

    #pragma unroll
    for (int mi = 0; mi < 2; mi++) {
        #pragma unroll
        for (int nj = 0; nj < 8; nj++) {
            int row = m0 + wm * 32 + mi * 16 + g;
            int col = n0 + wn * 64 + nj * 8 + tc * 2;
            float b0 = __ldg(bias + col), b1 = __ldg(bias + col + 1);
            __half* dst = (col < 256) ? C1 : C2;
            int cc = (col < 256) ? col : col - 256;
            *reinterpret_cast<uint*>(dst + (size_t)row * 256 + cc) =
                pack_h(acc[mi][nj][0] + b0, acc[mi][nj][1] + b1);
            *reinterpret_cast<uint*>(dst + (size_t)(row + 8) * 256 + cc) =
                pack_h(acc[mi][nj][2] + b0, acc[mi][nj][3] + b1);
        }
    }
}

// =============================================================================
// Fused attention (fp16 in via cp.async + ldmatrix). O written hi-only.
// One CTA per (bt, head-group of 4). 256 threads, 2 CTAs/SM.
// =============================================================================
__global__ __launch_bounds__(256, 2) void attn_kernel(const float* __restrict__ rpb)
{
    extern __shared__ char smc[];
    const uint sb = sm_u32(smc);
    const uint QH = sb, QL = sb + 17408, KH = sb + 34816, VH = sb + 52224;
    float* srpb = reinterpret_cast<float*>(smc + 69632);

    const int tid = threadIdx.x;
    const int bt = blockIdx.x >> 1;
    const int hg = blockIdx.x & 1;
    const int b = bt >> 1;

    const __half* qh_src = g_qh + (size_t)b * (64 * 256) + hg * 128;
    const __half* ql_src = g_ql + (size_t)b * (64 * 256) + hg * 128;
    const __half* kh_src = g_kh + (size_t)bt * (64 * 256) + hg * 128;
    const __half* vh_src = g_vh + (size_t)bt * (64 * 256) + hg * 128;

    #pragma unroll
    for (int u = 0; u < 4; u++) {
        int f = tid + u * 256;
        int r = f >> 4;
        int cc = (f & 15) << 3;
        uint doff = (uint)(r * 136 + cc) * 2;
        size_t soff = (size_t)r * 256 + cc;
        CP16(QH + doff, qh_src + soff);
        CP16(QL + doff, ql_src + soff);
        CP16(KH + doff, kh_src + soff);
        CP16(VH + doff, vh_src + soff);
    }
    for (int i = tid; i < 450; i += 256)
        CP16(sb + 69632 + i * 16, rpb + i * 4);
    CP_COMMIT();
    CP_WAIT(0);
    __syncthreads();

    const int warp = tid >> 5, lane = tid & 31;
    const int hl = warp >> 1;
    const int h = hg * 4 + hl;
    const int half = warp & 1;
    const int g = lane >> 2, tc = lane & 3;
    const int r0 = half * 32;

    float S[2][8][4];
    #pragma unroll
    for (int i = 0; i < 2; i++)
        #pragma unroll
        for (int j = 0; j < 8; j++)
            #pragma unroll
            for (int e = 0; e < 4; e++) S[i][j][e] = 0.f;

    #pragma unroll
    for (int kk = 0; kk < 2; kk++) {
        const int kc0 = hl * 32 + kk * 16;
        uint ah[2][4], al[2][4];
        #pragma unroll
        for (int mi = 0; mi < 2; mi++) {
            int arow = r0 + mi * 16 + (lane & 15);
            int acol = kc0 + (lane >> 4) * 8;
            uint aoff = (uint)(arow * 136 + acol) * 2;
            ldsm_x4(ah[mi], QH + aoff);
            ldsm_x4(al[mi], QL + aoff);
        }
        #pragma unroll
        for (int nj = 0; nj < 8; nj++) {
            int brow = nj * 8 + (lane & 7);
            int bcol = kc0 + ((lane >> 3) & 1) * 8;
            uint bh[2];
            ldsm_x2(bh, KH + (uint)(brow * 136 + bcol) * 2);
            #pragma unroll
            for (int mi = 0; mi < 2; mi++) {
                mma16816f16(S[mi][nj], ah[mi], bh);
                mma16816f16(S[mi][nj], al[mi], bh);
            }
        }
    }

    const float scale = 0.17677669529663687f;
    #pragma unroll
    for (int mi = 0; mi < 2; mi++) {
        #pragma unroll
        for (int p = 0; p < 2; p++) {
            int row = r0 + mi * 16 + g + p * 8;
            int pi = row >> 3, pj = row & 7;
            float mx = -1e30f;
            #pragma unroll
            for (int nj = 0; nj < 8; nj++) {
                #pragma unroll
                for (int e = 0; e < 2; e++) {
                    int col = nj * 8 + tc * 2 + e;
                    int qi = col >> 3, qj = col & 7;
                    int rel = (pi - qi + 7) * 15 + (pj - qj + 7);
                    float s = S[mi][nj][p * 2 + e] * scale + srpb[rel * 8 + h];
                    S[mi][nj][p * 2 + e] = s;
                    mx = fmaxf(mx, s);
                }
            }
            mx = fmaxf(mx, __shfl_xor_sync(0xffffffffu, mx, 1));
            mx = fmaxf(mx, __shfl_xor_sync(0xffffffffu, mx, 2));
            float sum = 0.f;
            #pragma unroll
            for (int nj = 0; nj < 8; nj++) {
                #pragma unroll
                for (int e = 0; e < 2; e++) {
                    float pe = __expf(S[mi][nj][p * 2 + e] - mx);
                    S[mi][nj][p * 2 + e] = pe;
                    sum += pe;
                }
            }
            sum += __shfl_xor_sync(0xffffffffu, sum, 1);
            sum += __shfl_xor_sync(0xffffffffu, sum, 2);
            float inv = 1.f / sum;
            #pragma unroll
            for (int nj = 0; nj < 8; nj++) {
                S[mi][nj][p * 2 + 0] *= inv;
                S[mi][nj][p * 2 + 1] *= inv;
            }
        }
    }

    uint phi[2][8][2], plo[2][8][2];
    #pragma unroll
    for (int mi = 0; mi < 2; mi++)
        #pragma unroll
        for (int nj = 0; nj < 8; nj++) {
            packsplit_h(S[mi][nj][0], S[mi][nj][1], phi[mi][nj][0], plo[mi][nj][0]);
            packsplit_h(S[mi][nj][2], S[mi][nj][3], phi[mi][nj][1], plo[mi][nj][1]);
        }

    float O[2][4][4];
    #pragma unroll
    for (int i = 0; i < 2; i++)
        #pragma unroll
        for (int j = 0; j < 4; j++)
            #pragma unroll
            for (int e = 0; e < 4; e++) O[i][j][e] = 0.f;

    #pragma unroll
    for (int t = 0; t < 4; t++) {
        #pragma unroll
        for (int jn = 0; jn < 4; jn++) {
            int vrow = t * 16 + (lane & 7) + ((lane >> 3) & 1) * 8;
            int vcol = hl * 32 + jn * 8;
            uint bh[2];
            ldsm_x2t(bh, VH + (uint)(vrow * 136 + vcol) * 2);
            #pragma unroll
            for (int mi = 0; mi < 2; mi++) {
                uint pa[4] = {phi[mi][2 * t][0], phi[mi][2 * t][1],
                              phi[mi][2 * t + 1][0], phi[mi][2 * t + 1][1]};
                uint la[4] = {plo[mi][2 * t][0], plo[mi][2 * t][1],
                              plo[mi][2 * t + 1][0], plo[mi][2 * t + 1][1]};
                mma16816f16(O[mi][jn], pa, bh);
                mma16816f16(O[mi][jn], la, bh);
            }
        }
    }

    __half* doh = g_oh + (size_t)bt * (64 * 256);
    #pragma unroll
    for (int mi = 0; mi < 2; mi++) {
        #pragma unroll
        for (int jn = 0; jn < 4; jn++) {
            int row = r0 + mi * 16 + g;
            int col = h * 32 + jn * 8 + tc * 2;
            *reinterpret_cast<uint*>(doh + row * 256 + col) =
                pack_h(O[mi][jn][0], O[mi][jn][1]);
            *reinterpret_cast<uint*>(doh + (row + 8) * 256 + col) =
                pack_h(O[mi][jn][2], O[mi][jn][3]);
        }
    }
}

// =============================================================================
// proj GEMM: out = Oh[M,256] @ wp^T + bias (fp32 out). Pure cp.async both
// sides, hi-only. occ 2. stage halves: Ah 5120 | Bh 5120 -> 20480 B; x2.
// =============================================================================
__global__ __launch_bounds__(256, 2) void proj_kernel(
    const __half* __restrict__ Ahg, const __half* __restrict__ Bw,
    const float* __restrict__ bias, float* __restrict__ C)
{
    constexpr int K = 256, LDT = 40, STG_H = 10240;
    extern __shared__ __half smh[];
    const uint sb = sm_u32(smh);
    const int tid = threadIdx.x;
    const int m0 = blockIdx.y * 128, n0 = blockIdx.x * 128;

    auto cp_stage = [&](int kt, int s) {
        int k0 = kt * 32;
        #pragma unroll
        for (int u = 0; u < 2; u++) {
            int f = tid + u * 256;
            int r = f >> 2, c = (f & 3) << 3;
            uint da = sb + (uint)(s * STG_H + r * LDT + c) * 2;
            uint db = sb + (uint)(s * STG_H + 5120 + r * LDT + c) * 2;
            CP16(da, Ahg + (size_t)(m0 + r) * K + k0 + c);
            CP16(db, Bw + (size_t)(n0 + r) * K + k0 + c);
        }
        CP_COMMIT();
    };

    const int warp = tid >> 5, lane = tid & 31;
    const int wm = warp & 3, wn = warp >> 2;
    const int g = lane >> 2, tc = lane & 3;

    float acc[2][8][4];
    #pragma unroll
    for (int i = 0; i < 2; i++)
        #pragma unroll
        for (int j = 0; j < 8; j++)
            #pragma unroll
            for (int e = 0; e < 4; e++) acc[i][j][e] = 0.f;

    cp_stage(0, 0);
    cp_stage(1, 1);
    CP_WAIT(0);
    __syncthreads();

    #pragma unroll
    for (int kt = 0; kt < 8; kt++) {
        const __half* st = smh + (kt & 1) * STG_H;
        const __half* Ah = st;
        const __half* Bh = st + 5120;

        #pragma unroll
        for (int kk = 0; kk < 2; kk++) {
            const int kc = kk * 16 + tc * 2;
            uint ah[2][4];
            #pragma unroll
            for (int mi = 0; mi < 2; mi++) {
                int row = wm * 32 + mi * 16 + g;
                ah[mi][0] = lds_u32(Ah + row * LDT + kc);
                ah[mi][1] = lds_u32(Ah + (row + 8) * LDT + kc);
                ah[mi][2] = lds_u32(Ah + row * LDT + kc + 8);
                ah[mi][3] = lds_u32(Ah + (row + 8) * LDT + kc + 8);
            }
            #pragma unroll
            for (int nj = 0; nj < 8; nj++) {
                int n = wn * 64 + nj * 8 + g;
                uint bh[2];
                bh[0] = lds_u32(Bh + n * LDT + kc);
                bh[1] = lds_u32(Bh + n * LDT + kc + 8);
                #pragma unroll
                for (int mi = 0; mi < 2; mi++)
                    mma16816f16(acc[mi][nj], ah[mi], bh);
            }
        }
        __syncthreads();
        if (kt < 6) { cp_stage(kt + 2, kt & 1); CP_WAIT(1); __syncthreads(); }
        else if (kt == 6) { CP_WAIT(0); __syncthreads(); }
    }

    #pragma unroll
    for (int mi = 0; mi < 2; mi++) {
        #pragma unroll
        for (int nj = 0; nj < 8; nj++) {
            int row = m0 + wm * 32 + mi * 16 + g;
            int col = n0 + wn * 64 + nj * 8 + tc * 2;
            float b0 = __ldg(bias + col), b1 = __ldg(bias + col + 1);
            *reinterpret_cast<float2*>(C + (size_t)row * 256 + col) =
                make_float2(acc[mi][nj][0] + b0, acc[mi][nj][1] + b1);
            *reinterpret_cast<float2*>(C + (size_t)(row + 8) * 256 + col) =
                make_float2(acc[mi][nj][2] + b0, acc[mi][nj][3] + b1);
        }
    }
}

// =============================================================================
extern "C" void kernel_launch(void* const* d_in, const int* in_sizes, int n_in,
                              void* d_out, int out_size)
{
    const float* x      = (const float*)d_in[0];
    const float* memory = (const float*)d_in[1];
    const float* q_w    = (const float*)d_in[2];
    const float* q_b    = (const float*)d_in[3];
    const float* kv_w   = (const float*)d_in[4];
    const float* kv_b   = (const float*)d_in[5];
    const float* proj_w = (const float*)d_in[6];
    const float* proj_b = (const float*)d_in[7];
    const float* rpb    = (const float*)d_in[8];
    float* out = (float*)d_out;

    __half *qh, *ql, *kh, *vh, *oh, *wq, *wkv, *wp;
    cudaGetSymbolAddress((void**)&qh, g_qh);
    cudaGetSymbolAddress((void**)&ql, g_ql);
    cudaGetSymbolAddress((void**)&kh, g_kh);
    cudaGetSymbolAddress((void**)&vh, g_vh);
    cudaGetSymbolAddress((void**)&oh, g_oh);
    cudaGetSymbolAddress((void**)&wq, g_wq);
    cudaGetSymbolAddress((void**)&wkv, g_wkv);
    cudaGetSymbolAddress((void**)&wp, g_wp);

    cudaFuncSetAttribute(gemm_q_kernel,
                         cudaFuncAttributeMaxDynamicSharedMemorySize, 61440);
    cudaFuncSetAttribute(gemm_kv_kernel,
                         cudaFuncAttributeMaxDynamicSharedMemorySize, 40960);
    cudaFuncSetAttribute(attn_kernel,
                         cudaFuncAttributeMaxDynamicSharedMemorySize, 76832);
    cudaFuncSetAttribute(proj_kernel,
                         cudaFuncAttributeMaxDynamicSharedMemorySize, 40960);

    // pre-convert weights to fp16
    wconv_kernel<<<128, 256>>>(q_w, kv_w, proj_w);
    // q projection -> qh/ql planes
    gemm_q_kernel<<<dim3(2, 1024), 256, 61440>>>(x, wq, q_b, qh, ql);
    // kv projection (hi-only) -> kh, vh
    gemm_kv_kernel<<<dim3(4, 2048), 256, 40960>>>(memory, wkv, kv_b, kh, vh);
    // fused attention -> oh
    attn_kernel<<<8192, 256, 76832>>>(rpb);
    // output projection (hi-only) -> fp32 out
    proj_kernel<<<dim3(2, 2048), 256, 40960>>>(oh, wp, proj_b, out);
}